// round 9
// baseline (speedup 1.0000x reference)
#include <cuda_runtime.h>
#include <cstdint>

#define LQv 2048
#define BZv 8
#define Dv 1024
#define NHv 16
#define NKv 4
#define FFv 2048
#define HDv 64
#define MROWS (LQv * BZv)   // 16384

// ================= scratch (single blob, no allocations) =================
#define MDsz ((size_t)MROWS * Dv)
#define OFF_Q     ((size_t)0)
#define OFF_VAL   (OFF_Q   + MDsz)
#define OFF_OFFA  (OFF_VAL + MDsz)                       // [MROWS,128]
#define OFF_AO    (OFF_OFFA + (size_t)MROWS * 128)
#define OFF_X     (OFF_AO  + MDsz)
#define OFF_XR    (OFF_X   + MDsz)
#define OFF_Y     (OFF_XR  + MDsz)
#define OFF_H     (OFF_Y   + MDsz)                       // [MROWS,FF]
#define OFF_SRCR  (OFF_H   + (size_t)MROWS * FFv)        // rounded src
#define OFF_WVR   (OFF_SRCR + MDsz)                      // [1024,1024]
#define OFF_WOR   (OFF_WVR + (size_t)Dv * Dv)
#define OFF_W1R   (OFF_WOR + (size_t)Dv * Dv)            // [1024,2048]
#define OFF_W2R   (OFF_W1R + (size_t)Dv * FFv)           // [2048,1024]
#define OFF_WOFA  (OFF_W2R + (size_t)FFv * Dv)           // [1024,128]
#define OFF_BOFA  (OFF_WOFA + (size_t)Dv * 128)          // [128]
#define SCRATCH_FLOATS (OFF_BOFA + 128)

__device__ float g_scratch[SCRATCH_FLOATS];

__device__ __forceinline__ uint32_t smem_u32(const void* p) {
    uint32_t a;
    asm("{ .reg .u64 t; cvta.to.shared.u64 t, %1; cvt.u32.u64 %0, t; }"
        : "=r"(a) : "l"(p));
    return a;
}
__device__ __forceinline__ float rn_tf32f(float x) {
    uint32_t u;
    asm("cvt.rn.tf32.f32 %0, %1;" : "=r"(u) : "f"(x));
    return __uint_as_float(u);
}

#define CP16(dst, src) \
    asm volatile("cp.async.cg.shared.global [%0], [%1], 16;" \
                 :: "r"(dst), "l"(src))
#define CP_COMMIT() asm volatile("cp.async.commit_group;")
#define CP_WAIT1()  asm volatile("cp.async.wait_group 1;")
#define CP_WAIT0()  asm volatile("cp.async.wait_group 0;")

// ================= round-copy: o[i] = tf32(a[i]) =================
__global__ __launch_bounds__(256)
void round_k(const float* __restrict__ a, float* __restrict__ o)
{
    size_t i = ((size_t)blockIdx.x * 256 + threadIdx.x) * 4;
    float4 v = *reinterpret_cast<const float4*>(a + i);
    v.x = rn_tf32f(v.x); v.y = rn_tf32f(v.y);
    v.z = rn_tf32f(v.z); v.w = rn_tf32f(v.w);
    *reinterpret_cast<float4*>(o + i) = v;
}

// ================= prep: fuse Woff|Wa -> Wofa[K=1024][N=128] (rounded) ======
__global__ __launch_bounds__(256)
void prep_offa_k(const float* __restrict__ Woff, const float* __restrict__ boff,
                 const float* __restrict__ Wa,   const float* __restrict__ ba,
                 float* __restrict__ Wofa, float* __restrict__ bout)
{
    int idx = blockIdx.x * 256 + threadIdx.x;   // 1024*128
    int k = idx >> 7, n = idx & 127;
    float v = (n < 64) ? Woff[(size_t)k * 64 + n] : Wa[(size_t)k * 64 + (n - 64)];
    Wofa[idx] = rn_tf32f(v);
    if (idx < 128) bout[idx] = (idx < 64) ? boff[idx] : ba[idx - 64];
}

// ================= add (rounded output; q only feeds a GEMM) ==============
__global__ __launch_bounds__(256)
void add_k(const float* __restrict__ a, const float* __restrict__ b,
           float* __restrict__ o)
{
    size_t i = ((size_t)blockIdx.x * 256 + threadIdx.x) * 4;
    float4 va = *reinterpret_cast<const float4*>(a + i);
    float4 vb = *reinterpret_cast<const float4*>(b + i);
    float4 vo;
    vo.x = rn_tf32f(va.x + vb.x); vo.y = rn_tf32f(va.y + vb.y);
    vo.z = rn_tf32f(va.z + vb.z); vo.w = rn_tf32f(va.w + vb.w);
    *reinterpret_cast<float4*>(o + i) = vo;
}

// ================= tf32 mma.sync GEMM =================
// C[M,N] = A[M,K] @ B[K,N] + bias (+epi). BM=256, BN=128, BK=32.
// 512 threads = 16 warps (4 M x 4 N), warp tile 64x32. 3-stage cp.async.
// Operands pre-rounded to tf32 — no in-loop cvt.
enum { EPI_BIAS = 0, EPI_MASK = 1, EPI_RELU = 2, EPI_RES = 3 };

#define SA 36
#define SB 136
#define A_F (256 * SA)            // 9216 floats
#define B_F (32 * SB)             // 4352 floats
#define STG_F (A_F + B_F)         // 13568 floats
#define GSMEM_BYTES (3 * STG_F * 4)   // 162816 B

__device__ __forceinline__ void mma_tf32(float* c, const uint32_t* a,
                                         const uint32_t* b)
{
    asm volatile(
        "mma.sync.aligned.m16n8k8.row.col.f32.tf32.tf32.f32 "
        "{%0,%1,%2,%3}, {%4,%5,%6,%7}, {%8,%9}, {%0,%1,%2,%3};"
        : "+f"(c[0]), "+f"(c[1]), "+f"(c[2]), "+f"(c[3])
        : "r"(a[0]), "r"(a[1]), "r"(a[2]), "r"(a[3]),
          "r"(b[0]), "r"(b[1]));
}

template <int EPI>
__global__ __launch_bounds__(512, 1)
void mma_gemm(const float* __restrict__ A, const float* __restrict__ B,
              const float* __restrict__ bias, const float* __restrict__ res,
              const unsigned char* __restrict__ mask,
              int K, int N, float* __restrict__ C)
{
    extern __shared__ float sm[];
    const uint32_t sb0 = smem_u32(sm);

    const int tid = threadIdx.x;
    const int lane = tid & 31;
    const int wid = tid >> 5;
    const int warp_m = wid & 3;        // 4 warps in M (64 rows each)
    const int warp_n = wid >> 2;       // 4 warps in N (32 cols each)
    const int g = lane >> 2, t = lane & 3;
    const int row0 = blockIdx.y * 256;
    const int col0 = blockIdx.x * 128;

    float acc[4][4][4];
#pragma unroll
    for (int mi = 0; mi < 4; mi++)
#pragma unroll
        for (int ni = 0; ni < 4; ni++)
#pragma unroll
            for (int j = 0; j < 4; j++) acc[mi][ni][j] = 0.f;

    const int NC = K >> 5;

    auto issue = [&](int c_, int s_) {
        const float* Ap = A + (size_t)row0 * K + (c_ << 5);
        const float* Bp = B + (size_t)(c_ << 5) * N + col0;
        uint32_t ab = sb0 + (uint32_t)s_ * (STG_F * 4);
        uint32_t bb = ab + A_F * 4;
#pragma unroll
        for (int it = 0; it < 4; it++) {        // A: 256x32 = 2048 float4
            int id = tid + it * 512;
            int m = id >> 3, kc = id & 7;
            CP16(ab + (uint32_t)(m * SA + kc * 4) * 4,
                 Ap + (size_t)m * K + kc * 4);
        }
#pragma unroll
        for (int it = 0; it < 2; it++) {        // B: 32x128 = 1024 float4
            int id = tid + it * 512;
            int k = id >> 5, nc = id & 31;
            CP16(bb + (uint32_t)(k * SB + nc * 4) * 4,
                 Bp + (size_t)k * N + nc * 4);
        }
        CP_COMMIT();
    };

    issue(0, 0);
    issue(1, 1);

    for (int c = 0; c < NC; c++) {
        const int s = c % 3;
        if (c + 2 < NC) { CP_WAIT1(); } else { CP_WAIT0(); }
        __syncthreads();
        if (c + 2 < NC) issue(c + 2, (c + 2) % 3);

        const float* as = sm + s * STG_F;
        const float* bs = as + A_F;
#pragma unroll
        for (int kk = 0; kk < 4; kk++) {
            uint32_t af[4][4], bf[4][2];
#pragma unroll
            for (int mi = 0; mi < 4; mi++) {
                int base = (warp_m * 64 + mi * 16 + g) * SA + kk * 8 + t;
                af[mi][0] = __float_as_uint(as[base]);
                af[mi][1] = __float_as_uint(as[base + 8 * SA]);
                af[mi][2] = __float_as_uint(as[base + 4]);
                af[mi][3] = __float_as_uint(as[base + 8 * SA + 4]);
            }
#pragma unroll
            for (int ni = 0; ni < 4; ni++) {
                int bb = (kk * 8 + t) * SB + warp_n * 32 + ni * 8 + g;
                bf[ni][0] = __float_as_uint(bs[bb]);
                bf[ni][1] = __float_as_uint(bs[bb + 4 * SB]);
            }
#pragma unroll
            for (int mi = 0; mi < 4; mi++)
#pragma unroll
                for (int ni = 0; ni < 4; ni++)
                    mma_tf32(acc[mi][ni], af[mi], bf[ni]);
        }
    }

    // ---- epilogue ----
#pragma unroll
    for (int mi = 0; mi < 4; mi++) {
        int rA = row0 + warp_m * 64 + mi * 16 + g;     // rows rA, rA+8
#pragma unroll
        for (int half = 0; half < 2; half++) {
            int r = rA + half * 8;
            unsigned char mrow = 0;
            if (EPI == EPI_MASK) {
                int b = r & (BZv - 1);
                int qq = r >> 3;
                mrow = mask[b * LQv + qq];
            }
#pragma unroll
            for (int ni = 0; ni < 4; ni++) {
                int cc = col0 + warp_n * 32 + ni * 8 + t * 2;
                float v0 = acc[mi][ni][half * 2 + 0] + bias[cc + 0];
                float v1 = acc[mi][ni][half * 2 + 1] + bias[cc + 1];
                if (EPI == EPI_MASK && mrow) { v0 = 0.f; v1 = 0.f; }
                if (EPI == EPI_RELU) {
                    v0 = rn_tf32f(fmaxf(v0, 0.f));
                    v1 = rn_tf32f(fmaxf(v1, 0.f));
                }
                if (EPI == EPI_RES) {
                    float2 rv = *reinterpret_cast<const float2*>(
                        &res[(size_t)r * N + cc]);
                    v0 += rv.x; v1 += rv.y;
                }
                *reinterpret_cast<float2*>(&C[(size_t)r * N + cc]) =
                    make_float2(v0, v1);
            }
        }
    }
}

// ================= softmax + grid_sample1d + head combine =================
__global__ __launch_bounds__(256)
void sample_k(const float* __restrict__ value,   // [Lv, BZ, D]
              const float* __restrict__ offa,    // [MROWS, 128]
              const float* __restrict__ refp,    // [BZ, LQ]
              const float* __restrict__ snip,    // [BZ]
              float* __restrict__ out)           // [MROWS, D]
{
    int t = blockIdx.x * 256 + threadIdx.x;
    int c = t & 63;
    int gidx = t >> 6;
    int h = gidx & (NHv - 1);
    int rb = gidx >> 4;
    int b = rb & (BZv - 1);
    int q = rb >> 3;

    const float* ol = offa + (size_t)rb * 128 + h * NKv;
    const float* al = ol + 64;

    float a0 = al[0], a1 = al[1], a2 = al[2], a3 = al[3];
    float m = fmaxf(fmaxf(a0, a1), fmaxf(a2, a3));
    float e0 = __expf(a0 - m), e1 = __expf(a1 - m);
    float e2 = __expf(a2 - m), e3 = __expf(a3 - m);
    float inv_s = 1.f / (e0 + e1 + e2 + e3);
    float ak[4] = {e0 * inv_s, e1 * inv_s, e2 * inv_s, e3 * inv_s};

    float refv = refp[b * LQv + q];
    float inv_sn = 1.f / snip[b];

    float acc = 0.f;
#pragma unroll
    for (int k = 0; k < NKv; k++) {
        float loc = refv + ol[k] * inv_sn;
        float x = loc * (float)(LQv - 1);
        float x0f = floorf(x);
        float w1 = x - x0f;
        float w0 = 1.f - w1;
        float x0c = fminf(fmaxf(x0f, -2.f), (float)(LQv + 1));
        int i0 = (int)x0c;
        int i1 = i0 + 1;
        float v0 = 0.f, v1 = 0.f;
        if (x0f >= 0.f && x0f <= (float)(LQv - 1))
            v0 = value[((size_t)i0 * BZv + b) * Dv + h * HDv + c];
        if (x0f >= -1.f && x0f <= (float)(LQv - 2))
            v1 = value[((size_t)i1 * BZv + b) * Dv + h * HDv + c];
        acc += ak[k] * (w0 * v0 + w1 * v1);
    }
    out[(size_t)rb * Dv + h * HDv + c] = rn_tf32f(acc);
}

// ================= LayerNorm D=1024 (optional dual output) ================
__global__ __launch_bounds__(256)
void ln_k(const float* __restrict__ in, const float* __restrict__ gam,
          const float* __restrict__ bet, float* __restrict__ out,
          float* __restrict__ out_r)
{
    int row = blockIdx.x;
    const float* xp = in + (size_t)row * Dv;
    int c4 = threadIdx.x * 4;
    float4 v = *reinterpret_cast<const float4*>(&xp[c4]);
    float s  = v.x + v.y + v.z + v.w;
    float ss = v.x * v.x + v.y * v.y + v.z * v.z + v.w * v.w;
#pragma unroll
    for (int o = 16; o > 0; o >>= 1) {
        s  += __shfl_xor_sync(0xffffffffu, s, o);
        ss += __shfl_xor_sync(0xffffffffu, ss, o);
    }
    __shared__ float sh_s[8], sh_ss[8];
    int w = threadIdx.x >> 5;
    if ((threadIdx.x & 31) == 0) { sh_s[w] = s; sh_ss[w] = ss; }
    __syncthreads();
    s = 0.f; ss = 0.f;
#pragma unroll
    for (int i = 0; i < 8; i++) { s += sh_s[i]; ss += sh_ss[i]; }
    float mean = s * (1.f / Dv);
    float var  = ss * (1.f / Dv) - mean * mean;
    float inv  = rsqrtf(var + 1e-5f);
    float4 gv = *reinterpret_cast<const float4*>(&gam[c4]);
    float4 bvv = *reinterpret_cast<const float4*>(&bet[c4]);
    float4 o;
    o.x = (v.x - mean) * inv * gv.x + bvv.x;
    o.y = (v.y - mean) * inv * gv.y + bvv.y;
    o.z = (v.z - mean) * inv * gv.z + bvv.z;
    o.w = (v.w - mean) * inv * gv.w + bvv.w;
    *reinterpret_cast<float4*>(&out[(size_t)row * Dv + c4]) = o;
    if (out_r) {
        float4 r;
        r.x = rn_tf32f(o.x); r.y = rn_tf32f(o.y);
        r.z = rn_tf32f(o.z); r.w = rn_tf32f(o.w);
        *reinterpret_cast<float4*>(&out_r[(size_t)row * Dv + c4]) = r;
    }
}

// ================= launch =================
extern "C" void kernel_launch(void* const* d_in, const int* in_sizes, int n_in,
                              void* d_out, int out_size)
{
    const float* src  = (const float*)d_in[0];
    const float* pos  = (const float*)d_in[1];
    const unsigned char* mask = (const unsigned char*)d_in[2];
    const float* refp = (const float*)d_in[3];
    const float* snip = (const float*)d_in[4];
    const float* Wv   = (const float*)d_in[5];
    const float* bv   = (const float*)d_in[6];
    const float* Woff = (const float*)d_in[7];
    const float* boff = (const float*)d_in[8];
    const float* Wa   = (const float*)d_in[9];
    const float* ba   = (const float*)d_in[10];
    const float* Wo   = (const float*)d_in[11];
    const float* bo   = (const float*)d_in[12];
    const float* W1   = (const float*)d_in[13];
    const float* b1   = (const float*)d_in[14];
    const float* W2   = (const float*)d_in[15];
    const float* b2   = (const float*)d_in[16];
    const float* g1   = (const float*)d_in[17];
    const float* be1  = (const float*)d_in[18];
    const float* g2   = (const float*)d_in[19];
    const float* be2  = (const float*)d_in[20];
    float* outp = (float*)d_out;

    float* scratch = nullptr;
    cudaGetSymbolAddress((void**)&scratch, g_scratch);
    float* q    = scratch + OFF_Q;
    float* val  = scratch + OFF_VAL;
    float* offa = scratch + OFF_OFFA;
    float* ao   = scratch + OFF_AO;
    float* x    = scratch + OFF_X;
    float* xr   = scratch + OFF_XR;
    float* y    = scratch + OFF_Y;
    float* hh   = scratch + OFF_H;
    float* srcr = scratch + OFF_SRCR;
    float* wvr  = scratch + OFF_WVR;
    float* wor  = scratch + OFF_WOR;
    float* w1r  = scratch + OFF_W1R;
    float* w2r  = scratch + OFF_W2R;
    float* wofa = scratch + OFF_WOFA;
    float* bofa = scratch + OFF_BOFA;

    cudaFuncSetAttribute(mma_gemm<EPI_MASK>,
        cudaFuncAttributeMaxDynamicSharedMemorySize, GSMEM_BYTES);
    cudaFuncSetAttribute(mma_gemm<EPI_BIAS>,
        cudaFuncAttributeMaxDynamicSharedMemorySize, GSMEM_BYTES);
    cudaFuncSetAttribute(mma_gemm<EPI_RELU>,
        cudaFuncAttributeMaxDynamicSharedMemorySize, GSMEM_BYTES);
    cudaFuncSetAttribute(mma_gemm<EPI_RES>,
        cudaFuncAttributeMaxDynamicSharedMemorySize, GSMEM_BYTES);

    const dim3 blk(256);
    const dim3 gblk(512);

    // ---- prep: pre-round GEMM operands to tf32 ----
    round_k<<<(MDsz / 4) / 256, blk>>>(src, srcr);
    round_k<<<((size_t)Dv * Dv / 4) / 256, blk>>>(Wv, wvr);
    round_k<<<((size_t)Dv * Dv / 4) / 256, blk>>>(Wo, wor);
    round_k<<<((size_t)Dv * FFv / 4) / 256, blk>>>(W1, w1r);
    round_k<<<((size_t)FFv * Dv / 4) / 256, blk>>>(W2, w2r);
    prep_offa_k<<<(Dv * 128) / 256, blk>>>(Woff, boff, Wa, ba, wofa, bofa);

    // q = tf32(src + pos)
    add_k<<<(MDsz / 4) / 256, blk>>>(src, pos, q);

    // value = src @ Wv + bv (masked)
    mma_gemm<EPI_MASK><<<dim3(Dv / 128, MROWS / 256), gblk, GSMEM_BYTES>>>(
        srcr, wvr, bv, nullptr, mask, Dv, Dv, val);

    // offsets + attn logits fused: [MROWS,128]
    mma_gemm<EPI_BIAS><<<dim3(1, MROWS / 256), gblk, GSMEM_BYTES>>>(
        q, wofa, bofa, nullptr, nullptr, Dv, 128, offa);

    // softmax + grid-sample + combine (rounded out)
    sample_k<<<(size_t)MROWS * NHv * HDv / 256, blk>>>(val, offa, refp, snip, ao);

    // out proj + residual, LN1 (dual out: exact x + rounded xr)
    mma_gemm<EPI_RES><<<dim3(Dv / 128, MROWS / 256), gblk, GSMEM_BYTES>>>(
        ao, wor, bo, src, nullptr, Dv, Dv, y);
    ln_k<<<MROWS, blk>>>(y, g1, be1, x, xr);

    // FFN
    mma_gemm<EPI_RELU><<<dim3(FFv / 128, MROWS / 256), gblk, GSMEM_BYTES>>>(
        xr, w1r, b1, nullptr, nullptr, Dv, FFv, hh);
    mma_gemm<EPI_RES><<<dim3(Dv / 128, MROWS / 256), gblk, GSMEM_BYTES>>>(
        hh, w2r, b2, x, nullptr, FFv, Dv, y);
    ln_k<<<MROWS, blk>>>(y, g2, be2, outp, nullptr);
}

// round 10
// speedup vs baseline: 1.0476x; 1.0476x over previous
#include <cuda_runtime.h>
#include <cstdint>

#define LQv 2048
#define BZv 8
#define Dv 1024
#define NHv 16
#define NKv 4
#define FFv 2048
#define HDv 64
#define MROWS (LQv * BZv)   // 16384

// ================= scratch (single blob, no allocations) =================
#define MDsz ((size_t)MROWS * Dv)
#define OFF_Q     ((size_t)0)
#define OFF_VAL   (OFF_Q   + MDsz)
#define OFF_OFFA  (OFF_VAL + MDsz)                       // [MROWS,128]
#define OFF_AO    (OFF_OFFA + (size_t)MROWS * 128)
#define OFF_X     (OFF_AO  + MDsz)
#define OFF_XR    (OFF_X   + MDsz)
#define OFF_Y     (OFF_XR  + MDsz)
#define OFF_H     (OFF_Y   + MDsz)                       // [MROWS,FF]
#define OFF_SRCR  (OFF_H   + (size_t)MROWS * FFv)        // rounded src
#define OFF_WVR   (OFF_SRCR + MDsz)                      // [1024,1024]
#define OFF_WOR   (OFF_WVR + (size_t)Dv * Dv)
#define OFF_W1R   (OFF_WOR + (size_t)Dv * Dv)            // [1024,2048]
#define OFF_W2R   (OFF_W1R + (size_t)Dv * FFv)           // [2048,1024]
#define OFF_WOFA  (OFF_W2R + (size_t)FFv * Dv)           // [1024,128]
#define OFF_BOFA  (OFF_WOFA + (size_t)Dv * 128)          // [128]
#define SCRATCH_FLOATS (OFF_BOFA + 128)

__device__ float g_scratch[SCRATCH_FLOATS];

__device__ __forceinline__ uint32_t smem_u32(const void* p) {
    uint32_t a;
    asm("{ .reg .u64 t; cvta.to.shared.u64 t, %1; cvt.u32.u64 %0, t; }"
        : "=r"(a) : "l"(p));
    return a;
}
__device__ __forceinline__ float rn_tf32f(float x) {
    uint32_t u;
    asm("cvt.rn.tf32.f32 %0, %1;" : "=r"(u) : "f"(x));
    return __uint_as_float(u);
}

#define CP16(dst, src) \
    asm volatile("cp.async.cg.shared.global [%0], [%1], 16;" \
                 :: "r"(dst), "l"(src))
#define CP_COMMIT() asm volatile("cp.async.commit_group;")
#define CP_WAIT1()  asm volatile("cp.async.wait_group 1;")
#define CP_WAIT0()  asm volatile("cp.async.wait_group 0;")

// ================= round-copy: o[i] = tf32(a[i]) =================
__global__ __launch_bounds__(256)
void round_k(const float* __restrict__ a, float* __restrict__ o)
{
    size_t i = ((size_t)blockIdx.x * 256 + threadIdx.x) * 4;
    float4 v = *reinterpret_cast<const float4*>(a + i);
    v.x = rn_tf32f(v.x); v.y = rn_tf32f(v.y);
    v.z = rn_tf32f(v.z); v.w = rn_tf32f(v.w);
    *reinterpret_cast<float4*>(o + i) = v;
}

// ================= prep: fuse Woff|Wa -> Wofa[K=1024][N=128] (rounded) ======
__global__ __launch_bounds__(256)
void prep_offa_k(const float* __restrict__ Woff, const float* __restrict__ boff,
                 const float* __restrict__ Wa,   const float* __restrict__ ba,
                 float* __restrict__ Wofa, float* __restrict__ bout)
{
    int idx = blockIdx.x * 256 + threadIdx.x;   // 1024*128
    int k = idx >> 7, n = idx & 127;
    float v = (n < 64) ? Woff[(size_t)k * 64 + n] : Wa[(size_t)k * 64 + (n - 64)];
    Wofa[idx] = rn_tf32f(v);
    if (idx < 128) bout[idx] = (idx < 64) ? boff[idx] : ba[idx - 64];
}

// ================= add (rounded; q only feeds a GEMM) ==============
__global__ __launch_bounds__(256)
void add_k(const float* __restrict__ a, const float* __restrict__ b,
           float* __restrict__ o)
{
    size_t i = ((size_t)blockIdx.x * 256 + threadIdx.x) * 4;
    float4 va = *reinterpret_cast<const float4*>(a + i);
    float4 vb = *reinterpret_cast<const float4*>(b + i);
    float4 vo;
    vo.x = rn_tf32f(va.x + vb.x); vo.y = rn_tf32f(va.y + vb.y);
    vo.z = rn_tf32f(va.z + vb.z); vo.w = rn_tf32f(va.w + vb.w);
    *reinterpret_cast<float4*>(o + i) = vo;
}

// ================= tf32 mma.sync GEMM =================
// C[M,N] = A[M,K] @ B[K,N] + bias (+epi). BM=128, BN=NI*32, BK=32, 256 thr.
// 8 warps: 2 in M (64 rows) x 4 in N (NI*8 cols). 3-stage cp.async, wait 1.
// Operands pre-rounded to tf32 — no in-loop cvt.
enum { EPI_BIAS = 0, EPI_MASK = 1, EPI_RELU = 2, EPI_RES = 3 };

#define SA 36
#define A_F (128 * SA)            // 4608 floats

__device__ __forceinline__ void mma_tf32(float* c, const uint32_t* a,
                                         const uint32_t* b)
{
    asm volatile(
        "mma.sync.aligned.m16n8k8.row.col.f32.tf32.tf32.f32 "
        "{%0,%1,%2,%3}, {%4,%5,%6,%7}, {%8,%9}, {%0,%1,%2,%3};"
        : "+f"(c[0]), "+f"(c[1]), "+f"(c[2]), "+f"(c[3])
        : "r"(a[0]), "r"(a[1]), "r"(a[2]), "r"(a[3]),
          "r"(b[0]), "r"(b[1]));
}

template <int NI, int EPI>
__global__ __launch_bounds__(256, 1)
void mma_gemm(const float* __restrict__ A, const float* __restrict__ B,
              const float* __restrict__ bias, const float* __restrict__ res,
              const unsigned char* __restrict__ mask,
              int K, int N, float* __restrict__ C)
{
    constexpr int BN  = NI * 32;          // 128 or 256
    constexpr int SB  = BN + 8;
    constexpr int B_F = 32 * SB;
    constexpr int STG_F = A_F + B_F;
    constexpr int BCP = BN / 32;          // B granules/thread (4 or 8)

    extern __shared__ float sm[];
    const uint32_t sb0 = smem_u32(sm);

    const int tid = threadIdx.x;
    const int lane = tid & 31;
    const int wid = tid >> 5;
    const int warp_m = wid & 1;
    const int warp_n = wid >> 1;
    const int g = lane >> 2, t = lane & 3;
    const int row0 = blockIdx.y * 128;
    const int col0 = blockIdx.x * BN;

    float acc[4][NI][4];
#pragma unroll
    for (int mi = 0; mi < 4; mi++)
#pragma unroll
        for (int ni = 0; ni < NI; ni++)
#pragma unroll
            for (int j = 0; j < 4; j++) acc[mi][ni][j] = 0.f;

    const int NC = K >> 5;

    auto issue = [&](int c_, int s_) {
        const float* Ap = A + (size_t)row0 * K + (c_ << 5);
        const float* Bp = B + (size_t)(c_ << 5) * N + col0;
        uint32_t ab = sb0 + (uint32_t)s_ * (STG_F * 4);
        uint32_t bb = ab + A_F * 4;
#pragma unroll
        for (int it = 0; it < 4; it++) {
            int id = tid + it * 256;
            int m = id >> 3, kc = id & 7;
            CP16(ab + (uint32_t)(m * SA + kc * 4) * 4,
                 Ap + (size_t)m * K + kc * 4);
        }
#pragma unroll
        for (int it = 0; it < BCP; it++) {
            int id = tid + it * 256;
            int k = id / (BN / 4), nc = id % (BN / 4);
            CP16(bb + (uint32_t)(k * SB + nc * 4) * 4,
                 Bp + (size_t)k * N + nc * 4);
        }
        CP_COMMIT();
    };

    issue(0, 0);
    issue(1, 1);

    for (int c = 0; c < NC; c++) {
        const int s = c % 3;
        if (c + 2 < NC) { CP_WAIT1(); } else { CP_WAIT0(); }
        __syncthreads();
        if (c + 2 < NC) issue(c + 2, (c + 2) % 3);

        const float* as = sm + s * STG_F;
        const float* bs = as + A_F;
#pragma unroll
        for (int kk = 0; kk < 4; kk++) {
            uint32_t af[4][4], bf[NI][2];
#pragma unroll
            for (int mi = 0; mi < 4; mi++) {
                int base = (warp_m * 64 + mi * 16 + g) * SA + kk * 8 + t;
                af[mi][0] = __float_as_uint(as[base]);
                af[mi][1] = __float_as_uint(as[base + 8 * SA]);
                af[mi][2] = __float_as_uint(as[base + 4]);
                af[mi][3] = __float_as_uint(as[base + 8 * SA + 4]);
            }
#pragma unroll
            for (int ni = 0; ni < NI; ni++) {
                int bb = (kk * 8 + t) * SB + warp_n * (NI * 8) + ni * 8 + g;
                bf[ni][0] = __float_as_uint(bs[bb]);
                bf[ni][1] = __float_as_uint(bs[bb + 4 * SB]);
            }
#pragma unroll
            for (int mi = 0; mi < 4; mi++)
#pragma unroll
                for (int ni = 0; ni < NI; ni++)
                    mma_tf32(acc[mi][ni], af[mi], bf[ni]);
        }
    }

    // ---- epilogue ----
#pragma unroll
    for (int mi = 0; mi < 4; mi++) {
        int rA = row0 + warp_m * 64 + mi * 16 + g;
#pragma unroll
        for (int half = 0; half < 2; half++) {
            int r = rA + half * 8;
            unsigned char mrow = 0;
            if (EPI == EPI_MASK) {
                int b = r & (BZv - 1);
                int qq = r >> 3;
                mrow = mask[b * LQv + qq];
            }
#pragma unroll
            for (int ni = 0; ni < NI; ni++) {
                int cc = col0 + warp_n * (NI * 8) + ni * 8 + t * 2;
                float v0 = acc[mi][ni][half * 2 + 0] + bias[cc + 0];
                float v1 = acc[mi][ni][half * 2 + 1] + bias[cc + 1];
                if (EPI == EPI_MASK && mrow) { v0 = 0.f; v1 = 0.f; }
                if (EPI == EPI_RELU) {
                    v0 = rn_tf32f(fmaxf(v0, 0.f));
                    v1 = rn_tf32f(fmaxf(v1, 0.f));
                }
                if (EPI == EPI_RES) {
                    float2 rv = *reinterpret_cast<const float2*>(
                        &res[(size_t)r * N + cc]);
                    v0 += rv.x; v1 += rv.y;
                }
                *reinterpret_cast<float2*>(&C[(size_t)r * N + cc]) =
                    make_float2(v0, v1);
            }
        }
    }
}

#define SMB(NI_) ((3 * (A_F + 32 * ((NI_) * 32 + 8))) * 4)

// ================= softmax + grid_sample1d + head combine =================
__global__ __launch_bounds__(256)
void sample_k(const float* __restrict__ value,   // [Lv, BZ, D]
              const float* __restrict__ offa,    // [MROWS, 128]
              const float* __restrict__ refp,    // [BZ, LQ]
              const float* __restrict__ snip,    // [BZ]
              float* __restrict__ out)           // [MROWS, D]
{
    int t = blockIdx.x * 256 + threadIdx.x;
    int c = t & 63;
    int gidx = t >> 6;
    int h = gidx & (NHv - 1);
    int rb = gidx >> 4;
    int b = rb & (BZv - 1);
    int q = rb >> 3;

    const float* ol = offa + (size_t)rb * 128 + h * NKv;
    const float* al = ol + 64;

    float a0 = al[0], a1 = al[1], a2 = al[2], a3 = al[3];
    float m = fmaxf(fmaxf(a0, a1), fmaxf(a2, a3));
    float e0 = __expf(a0 - m), e1 = __expf(a1 - m);
    float e2 = __expf(a2 - m), e3 = __expf(a3 - m);
    float inv_s = 1.f / (e0 + e1 + e2 + e3);
    float ak[4] = {e0 * inv_s, e1 * inv_s, e2 * inv_s, e3 * inv_s};

    float refv = refp[b * LQv + q];
    float inv_sn = 1.f / snip[b];

    float acc = 0.f;
#pragma unroll
    for (int k = 0; k < NKv; k++) {
        float loc = refv + ol[k] * inv_sn;
        float x = loc * (float)(LQv - 1);
        float x0f = floorf(x);
        float w1 = x - x0f;
        float w0 = 1.f - w1;
        float x0c = fminf(fmaxf(x0f, -2.f), (float)(LQv + 1));
        int i0 = (int)x0c;
        int i1 = i0 + 1;
        float v0 = 0.f, v1 = 0.f;
        if (x0f >= 0.f && x0f <= (float)(LQv - 1))
            v0 = value[((size_t)i0 * BZv + b) * Dv + h * HDv + c];
        if (x0f >= -1.f && x0f <= (float)(LQv - 2))
            v1 = value[((size_t)i1 * BZv + b) * Dv + h * HDv + c];
        acc += ak[k] * (w0 * v0 + w1 * v1);
    }
    out[(size_t)rb * Dv + h * HDv + c] = rn_tf32f(acc);
}

// ================= LayerNorm D=1024 (optional dual output) ================
__global__ __launch_bounds__(256)
void ln_k(const float* __restrict__ in, const float* __restrict__ gam,
          const float* __restrict__ bet, float* __restrict__ out,
          float* __restrict__ out_r)
{
    int row = blockIdx.x;
    const float* xp = in + (size_t)row * Dv;
    int c4 = threadIdx.x * 4;
    float4 v = *reinterpret_cast<const float4*>(&xp[c4]);
    float s  = v.x + v.y + v.z + v.w;
    float ss = v.x * v.x + v.y * v.y + v.z * v.z + v.w * v.w;
#pragma unroll
    for (int o = 16; o > 0; o >>= 1) {
        s  += __shfl_xor_sync(0xffffffffu, s, o);
        ss += __shfl_xor_sync(0xffffffffu, ss, o);
    }
    __shared__ float sh_s[8], sh_ss[8];
    int w = threadIdx.x >> 5;
    if ((threadIdx.x & 31) == 0) { sh_s[w] = s; sh_ss[w] = ss; }
    __syncthreads();
    s = 0.f; ss = 0.f;
#pragma unroll
    for (int i = 0; i < 8; i++) { s += sh_s[i]; ss += sh_ss[i]; }
    float mean = s * (1.f / Dv);
    float var  = ss * (1.f / Dv) - mean * mean;
    float inv  = rsqrtf(var + 1e-5f);
    float4 gv = *reinterpret_cast<const float4*>(&gam[c4]);
    float4 bvv = *reinterpret_cast<const float4*>(&bet[c4]);
    float4 o;
    o.x = (v.x - mean) * inv * gv.x + bvv.x;
    o.y = (v.y - mean) * inv * gv.y + bvv.y;
    o.z = (v.z - mean) * inv * gv.z + bvv.z;
    o.w = (v.w - mean) * inv * gv.w + bvv.w;
    *reinterpret_cast<float4*>(&out[(size_t)row * Dv + c4]) = o;
    if (out_r) {
        float4 r;
        r.x = rn_tf32f(o.x); r.y = rn_tf32f(o.y);
        r.z = rn_tf32f(o.z); r.w = rn_tf32f(o.w);
        *reinterpret_cast<float4*>(&out_r[(size_t)row * Dv + c4]) = r;
    }
}

// ================= launch =================
extern "C" void kernel_launch(void* const* d_in, const int* in_sizes, int n_in,
                              void* d_out, int out_size)
{
    const float* src  = (const float*)d_in[0];
    const float* pos  = (const float*)d_in[1];
    const unsigned char* mask = (const unsigned char*)d_in[2];
    const float* refp = (const float*)d_in[3];
    const float* snip = (const float*)d_in[4];
    const float* Wv   = (const float*)d_in[5];
    const float* bv   = (const float*)d_in[6];
    const float* Woff = (const float*)d_in[7];
    const float* boff = (const float*)d_in[8];
    const float* Wa   = (const float*)d_in[9];
    const float* ba   = (const float*)d_in[10];
    const float* Wo   = (const float*)d_in[11];
    const float* bo   = (const float*)d_in[12];
    const float* W1   = (const float*)d_in[13];
    const float* b1   = (const float*)d_in[14];
    const float* W2   = (const float*)d_in[15];
    const float* b2   = (const float*)d_in[16];
    const float* g1   = (const float*)d_in[17];
    const float* be1  = (const float*)d_in[18];
    const float* g2   = (const float*)d_in[19];
    const float* be2  = (const float*)d_in[20];
    float* outp = (float*)d_out;

    float* scratch = nullptr;
    cudaGetSymbolAddress((void**)&scratch, g_scratch);
    float* q    = scratch + OFF_Q;
    float* val  = scratch + OFF_VAL;
    float* offa = scratch + OFF_OFFA;
    float* ao   = scratch + OFF_AO;
    float* x    = scratch + OFF_X;
    float* xr   = scratch + OFF_XR;
    float* y    = scratch + OFF_Y;
    float* hh   = scratch + OFF_H;
    float* srcr = scratch + OFF_SRCR;
    float* wvr  = scratch + OFF_WVR;
    float* wor  = scratch + OFF_WOR;
    float* w1r  = scratch + OFF_W1R;
    float* w2r  = scratch + OFF_W2R;
    float* wofa = scratch + OFF_WOFA;
    float* bofa = scratch + OFF_BOFA;

    cudaFuncSetAttribute(mma_gemm<8, EPI_MASK>,
        cudaFuncAttributeMaxDynamicSharedMemorySize, SMB(8));
    cudaFuncSetAttribute(mma_gemm<4, EPI_BIAS>,
        cudaFuncAttributeMaxDynamicSharedMemorySize, SMB(4));
    cudaFuncSetAttribute(mma_gemm<8, EPI_RELU>,
        cudaFuncAttributeMaxDynamicSharedMemorySize, SMB(8));
    cudaFuncSetAttribute(mma_gemm<8, EPI_RES>,
        cudaFuncAttributeMaxDynamicSharedMemorySize, SMB(8));

    const dim3 blk(256);

    // ---- prep: pre-round GEMM operands to tf32 ----
    round_k<<<(MDsz / 4) / 256, blk>>>(src, srcr);
    round_k<<<((size_t)Dv * Dv / 4) / 256, blk>>>(Wv, wvr);
    round_k<<<((size_t)Dv * Dv / 4) / 256, blk>>>(Wo, wor);
    round_k<<<((size_t)Dv * FFv / 4) / 256, blk>>>(W1, w1r);
    round_k<<<((size_t)FFv * Dv / 4) / 256, blk>>>(W2, w2r);
    prep_offa_k<<<(Dv * 128) / 256, blk>>>(Woff, boff, Wa, ba, wofa, bofa);

    // q = tf32(src + pos)
    add_k<<<(MDsz / 4) / 256, blk>>>(src, pos, q);

    // value = src @ Wv + bv (masked)
    mma_gemm<8, EPI_MASK><<<dim3(Dv / 256, MROWS / 128), blk, SMB(8)>>>(
        srcr, wvr, bv, nullptr, mask, Dv, Dv, val);

    // offsets + attn logits fused: [MROWS,128]
    mma_gemm<4, EPI_BIAS><<<dim3(1, MROWS / 128), blk, SMB(4)>>>(
        q, wofa, bofa, nullptr, nullptr, Dv, 128, offa);

    // softmax + grid-sample + combine (rounded out)
    sample_k<<<(size_t)MROWS * NHv * HDv / 256, blk>>>(val, offa, refp, snip, ao);

    // out proj + residual, LN1 (dual out: exact x + rounded xr)
    mma_gemm<8, EPI_RES><<<dim3(Dv / 256, MROWS / 128), blk, SMB(8)>>>(
        ao, wor, bo, src, nullptr, Dv, Dv, y);
    ln_k<<<MROWS, blk>>>(y, g1, be1, x, xr);

    // FFN
    mma_gemm<8, EPI_RELU><<<dim3(FFv / 256, MROWS / 128), blk, SMB(8)>>>(
        xr, w1r, b1, nullptr, nullptr, Dv, FFv, hh);
    mma_gemm<8, EPI_RES><<<dim3(Dv / 256, MROWS / 128), blk, SMB(8)>>>(
        hh, w2r, b2, x, nullptr, FFv, Dv, y);
    ln_k<<<MROWS, blk>>>(y, g2, be2, outp, nullptr);
}

// round 11
// speedup vs baseline: 1.8861x; 1.8005x over previous
#include <cuda_runtime.h>
#include <cuda_fp16.h>
#include <cstdint>

#define LQv 2048
#define BZv 8
#define Dv 1024
#define NHv 16
#define NKv 4
#define FFv 2048
#define HDv 64
#define MROWS (LQv * BZv)   // 16384

// ================= scratch =================
#define MDsz ((size_t)MROWS * Dv)
// float blob
#define OFF_OFFA  ((size_t)0)                            // [MROWS,128]
#define OFF_X     (OFF_OFFA + (size_t)MROWS * 128)
#define OFF_Y     (OFF_X   + MDsz)
#define OFF_BOFA  (OFF_Y   + MDsz)                       // [128]
#define SCRATCH_F (OFF_BOFA + 128)
__device__ float g_scratch_f[SCRATCH_F];

// half blob (all offsets multiples of 8 -> 16B aligned)
#define HOFF_SRC   ((size_t)0)
#define HOFF_Q     (HOFF_SRC + MDsz)
#define HOFF_VAL   (HOFF_Q   + MDsz)
#define HOFF_AO    (HOFF_VAL + MDsz)
#define HOFF_XH    (HOFF_AO  + MDsz)
#define HOFF_H     (HOFF_XH  + MDsz)                     // [MROWS,FF]
#define HOFF_WV    (HOFF_H   + (size_t)MROWS * FFv)
#define HOFF_WO    (HOFF_WV  + (size_t)Dv * Dv)
#define HOFF_W1    (HOFF_WO  + (size_t)Dv * Dv)
#define HOFF_W2    (HOFF_W1  + (size_t)Dv * FFv)
#define HOFF_WOFA  (HOFF_W2  + (size_t)FFv * Dv)         // [1024,128]
#define SCRATCH_H  (HOFF_WOFA + (size_t)Dv * 128)
__device__ __half g_scratch_h[SCRATCH_H];

__device__ __forceinline__ uint32_t smem_u32(const void* p) {
    uint32_t a;
    asm("{ .reg .u64 t; cvta.to.shared.u64 t, %1; cvt.u32.u64 %0, t; }"
        : "=r"(a) : "l"(p));
    return a;
}

#define CP16(dst, src) \
    asm volatile("cp.async.cg.shared.global [%0], [%1], 16;" \
                 :: "r"(dst), "l"(src))
#define CP_COMMIT() asm volatile("cp.async.commit_group;")
#define CP_WAIT2()  asm volatile("cp.async.wait_group 2;")
#define CP_WAIT0()  asm volatile("cp.async.wait_group 0;")

#define LDSM_X4(r, addr) \
    asm volatile("ldmatrix.sync.aligned.m8n8.x4.shared.b16 {%0,%1,%2,%3}, [%4];" \
                 : "=r"((r)[0]), "=r"((r)[1]), "=r"((r)[2]), "=r"((r)[3]) \
                 : "r"(addr))
#define LDSM_X4_T(r, addr) \
    asm volatile("ldmatrix.sync.aligned.m8n8.x4.trans.shared.b16 {%0,%1,%2,%3}, [%4];" \
                 : "=r"((r)[0]), "=r"((r)[1]), "=r"((r)[2]), "=r"((r)[3]) \
                 : "r"(addr))

__device__ __forceinline__ void mma_f16(float* c, const uint32_t* a,
                                        const uint32_t* b)
{
    asm volatile(
        "mma.sync.aligned.m16n8k16.row.col.f32.f16.f16.f32 "
        "{%0,%1,%2,%3}, {%4,%5,%6,%7}, {%8,%9}, {%0,%1,%2,%3};"
        : "+f"(c[0]), "+f"(c[1]), "+f"(c[2]), "+f"(c[3])
        : "r"(a[0]), "r"(a[1]), "r"(a[2]), "r"(a[3]),
          "r"(b[0]), "r"(b[1]));
}

// ================= fp32 -> fp16 convert (8 elems/thread) =================
__global__ __launch_bounds__(256)
void tohalf_k(const float* __restrict__ a, __half* __restrict__ o)
{
    size_t i = ((size_t)blockIdx.x * 256 + threadIdx.x) * 8;
    float4 v0 = *reinterpret_cast<const float4*>(a + i);
    float4 v1 = *reinterpret_cast<const float4*>(a + i + 4);
    __half2 h[4];
    h[0] = __floats2half2_rn(v0.x, v0.y);
    h[1] = __floats2half2_rn(v0.z, v0.w);
    h[2] = __floats2half2_rn(v1.x, v1.y);
    h[3] = __floats2half2_rn(v1.z, v1.w);
    *reinterpret_cast<uint4*>(o + i) = *reinterpret_cast<uint4*>(h);
}

// q = half(src + pos)
__global__ __launch_bounds__(256)
void addhalf_k(const float* __restrict__ a, const float* __restrict__ b,
               __half* __restrict__ o)
{
    size_t i = ((size_t)blockIdx.x * 256 + threadIdx.x) * 8;
    float4 a0 = *reinterpret_cast<const float4*>(a + i);
    float4 a1 = *reinterpret_cast<const float4*>(a + i + 4);
    float4 b0 = *reinterpret_cast<const float4*>(b + i);
    float4 b1 = *reinterpret_cast<const float4*>(b + i + 4);
    __half2 h[4];
    h[0] = __floats2half2_rn(a0.x + b0.x, a0.y + b0.y);
    h[1] = __floats2half2_rn(a0.z + b0.z, a0.w + b0.w);
    h[2] = __floats2half2_rn(a1.x + b1.x, a1.y + b1.y);
    h[3] = __floats2half2_rn(a1.z + b1.z, a1.w + b1.w);
    *reinterpret_cast<uint4*>(o + i) = *reinterpret_cast<uint4*>(h);
}

// fuse Woff|Wa -> Wofa[1024][128] half + bias concat
__global__ __launch_bounds__(256)
void prep_offa_k(const float* __restrict__ Woff, const float* __restrict__ boff,
                 const float* __restrict__ Wa,   const float* __restrict__ ba,
                 __half* __restrict__ Wofa, float* __restrict__ bout)
{
    int idx = blockIdx.x * 256 + threadIdx.x;   // 1024*128
    int k = idx >> 7, n = idx & 127;
    float v = (n < 64) ? Woff[(size_t)k * 64 + n] : Wa[(size_t)k * 64 + (n - 64)];
    Wofa[idx] = __float2half(v);
    if (idx < 128) bout[idx] = (idx < 64) ? boff[idx] : ba[idx - 64];
}

// ================= fp16 mma GEMM =================
// C[M,N] = A[M,K]@B[K,N] + bias (+epi). BM=128, BN=128, BK=32, 256 thr, 8 warps.
// A/B half; C fp32 or half (OUTH). 4-stage cp.async. ldmatrix fragments.
enum { EPI_BIAS = 0, EPI_MASK = 1, EPI_RELU = 2, EPI_RES = 3 };

#define SA_H 40                    // A row stride in halfs (80B)
#define SB_H 136                   // B row stride in halfs (272B)
#define A_B (128 * SA_H * 2)       // 10240 B
#define B_B (32 * SB_H * 2)        // 8704 B
#define STG_B (A_B + B_B)          // 18944 B
#define GSMEM_BYTES (4 * STG_B)    // 75776 B

template <int EPI, int OUTH>
__global__ __launch_bounds__(256, 2)
void hmma_gemm(const __half* __restrict__ A, const __half* __restrict__ B,
               const float* __restrict__ bias, const float* __restrict__ res,
               const unsigned char* __restrict__ mask,
               int K, int N, void* __restrict__ Cv)
{
    extern __shared__ char sm[];
    const uint32_t sb0 = smem_u32(sm);

    const int tid = threadIdx.x;
    const int lane = tid & 31;
    const int wid = tid >> 5;
    const int warp_m = wid & 1;        // 2 warps in M (64 rows)
    const int warp_n = wid >> 1;       // 4 warps in N (32 cols)
    const int g = lane >> 2, t = lane & 3;
    const int row0 = blockIdx.y * 128;
    const int col0 = blockIdx.x * 128;

    float acc[4][4][4];
#pragma unroll
    for (int mi = 0; mi < 4; mi++)
#pragma unroll
        for (int ni = 0; ni < 4; ni++)
#pragma unroll
            for (int j = 0; j < 4; j++) acc[mi][ni][j] = 0.f;

    const int NC = K >> 5;

    auto issue = [&](int c_, int s_) {
        const __half* Ap = A + (size_t)row0 * K + (c_ << 5);
        const __half* Bp = B + (size_t)(c_ << 5) * N + col0;
        uint32_t ab = sb0 + (uint32_t)s_ * STG_B;
        uint32_t bb = ab + A_B;
#pragma unroll
        for (int it = 0; it < 2; it++) {        // A: 128 rows x 4 granules
            int id = tid + it * 256;
            int m = id >> 2, kc = id & 3;
            CP16(ab + (uint32_t)(m * (SA_H * 2) + kc * 16),
                 Ap + (size_t)m * K + kc * 8);
        }
#pragma unroll
        for (int it = 0; it < 2; it++) {        // B: 32 rows x 16 granules
            int id = tid + it * 256;
            int k = id >> 4, nc = id & 15;
            CP16(bb + (uint32_t)(k * (SB_H * 2) + nc * 16),
                 Bp + (size_t)k * N + nc * 8);
        }
        CP_COMMIT();
    };

    // ldmatrix per-thread address components
    const int rowA = (lane & 7) + 8 * ((lane >> 3) & 1);
    const int koffA = (lane >> 4) * 16;          // bytes (8 halfs)
    const int krowB = lane & 15;
    const int noffB = (lane >> 4) * 8;           // halfs

    issue(0, 0);
    issue(1, 1);
    issue(2, 2);

    for (int c = 0; c < NC; c++) {
        const int s = c & 3;
        if (c + 3 < NC) { CP_WAIT2(); } else { CP_WAIT0(); }
        __syncthreads();
        if (c + 3 < NC) issue(c + 3, (c + 3) & 3);

        const uint32_t ab = sb0 + (uint32_t)s * STG_B;
        const uint32_t bb = ab + A_B;
#pragma unroll
        for (int kk = 0; kk < 2; kk++) {
            uint32_t af[4][4], bf[4][2];
#pragma unroll
            for (int mi = 0; mi < 4; mi++) {
                uint32_t addr = ab +
                    (uint32_t)((warp_m * 64 + mi * 16 + rowA) * (SA_H * 2) +
                               kk * 32 + koffA);
                LDSM_X4(af[mi], addr);
            }
#pragma unroll
            for (int ni2 = 0; ni2 < 2; ni2++) {
                uint32_t r[4];
                uint32_t addr = bb +
                    (uint32_t)((kk * 16 + krowB) * (SB_H * 2) +
                               (warp_n * 32 + ni2 * 16 + noffB) * 2);
                LDSM_X4_T(r, addr);
                bf[ni2 * 2 + 0][0] = r[0]; bf[ni2 * 2 + 0][1] = r[1];
                bf[ni2 * 2 + 1][0] = r[2]; bf[ni2 * 2 + 1][1] = r[3];
            }
#pragma unroll
            for (int mi = 0; mi < 4; mi++)
#pragma unroll
                for (int ni = 0; ni < 4; ni++)
                    mma_f16(acc[mi][ni], af[mi], bf[ni]);
        }
    }

    // ---- epilogue ----
#pragma unroll
    for (int mi = 0; mi < 4; mi++) {
        int rA = row0 + warp_m * 64 + mi * 16 + g;
#pragma unroll
        for (int half_i = 0; half_i < 2; half_i++) {
            int r = rA + half_i * 8;
            unsigned char mrow = 0;
            if (EPI == EPI_MASK) {
                int b = r & (BZv - 1);
                int qq = r >> 3;
                mrow = mask[b * LQv + qq];
            }
#pragma unroll
            for (int ni = 0; ni < 4; ni++) {
                int cc = col0 + warp_n * 32 + ni * 8 + t * 2;
                float v0 = acc[mi][ni][half_i * 2 + 0] + bias[cc + 0];
                float v1 = acc[mi][ni][half_i * 2 + 1] + bias[cc + 1];
                if (EPI == EPI_MASK && mrow) { v0 = 0.f; v1 = 0.f; }
                if (EPI == EPI_RELU) { v0 = fmaxf(v0, 0.f); v1 = fmaxf(v1, 0.f); }
                if (EPI == EPI_RES) {
                    float2 rv = *reinterpret_cast<const float2*>(
                        &res[(size_t)r * N + cc]);
                    v0 += rv.x; v1 += rv.y;
                }
                if (OUTH) {
                    __half2 h = __floats2half2_rn(v0, v1);
                    *reinterpret_cast<__half2*>(
                        (__half*)Cv + (size_t)r * N + cc) = h;
                } else {
                    *reinterpret_cast<float2*>(
                        (float*)Cv + (size_t)r * N + cc) = make_float2(v0, v1);
                }
            }
        }
    }
}

// ================= softmax + grid_sample1d + head combine =================
__global__ __launch_bounds__(256)
void sample_k(const __half* __restrict__ value,  // [Lv, BZ, D] half
              const float* __restrict__ offa,    // [MROWS, 128]
              const float* __restrict__ refp,    // [BZ, LQ]
              const float* __restrict__ snip,    // [BZ]
              __half* __restrict__ out)          // [MROWS, D] half
{
    int t = blockIdx.x * 256 + threadIdx.x;
    int c = t & 63;
    int gidx = t >> 6;
    int h = gidx & (NHv - 1);
    int rb = gidx >> 4;
    int b = rb & (BZv - 1);
    int q = rb >> 3;

    const float* ol = offa + (size_t)rb * 128 + h * NKv;
    const float* al = ol + 64;

    float a0 = al[0], a1 = al[1], a2 = al[2], a3 = al[3];
    float m = fmaxf(fmaxf(a0, a1), fmaxf(a2, a3));
    float e0 = __expf(a0 - m), e1 = __expf(a1 - m);
    float e2 = __expf(a2 - m), e3 = __expf(a3 - m);
    float inv_s = 1.f / (e0 + e1 + e2 + e3);
    float ak[4] = {e0 * inv_s, e1 * inv_s, e2 * inv_s, e3 * inv_s};

    float refv = refp[b * LQv + q];
    float inv_sn = 1.f / snip[b];

    float acc = 0.f;
#pragma unroll
    for (int k = 0; k < NKv; k++) {
        float loc = refv + ol[k] * inv_sn;
        float x = loc * (float)(LQv - 1);
        float x0f = floorf(x);
        float w1 = x - x0f;
        float w0 = 1.f - w1;
        float x0c = fminf(fmaxf(x0f, -2.f), (float)(LQv + 1));
        int i0 = (int)x0c;
        int i1 = i0 + 1;
        float v0 = 0.f, v1 = 0.f;
        if (x0f >= 0.f && x0f <= (float)(LQv - 1))
            v0 = __half2float(value[((size_t)i0 * BZv + b) * Dv + h * HDv + c]);
        if (x0f >= -1.f && x0f <= (float)(LQv - 2))
            v1 = __half2float(value[((size_t)i1 * BZv + b) * Dv + h * HDv + c]);
        acc += ak[k] * (w0 * v0 + w1 * v1);
    }
    out[(size_t)rb * Dv + h * HDv + c] = __float2half(acc);
}

// ================= LayerNorm D=1024 (optional half dual output) ===========
__global__ __launch_bounds__(256)
void ln_k(const float* __restrict__ in, const float* __restrict__ gam,
          const float* __restrict__ bet, float* __restrict__ out,
          __half* __restrict__ out_h)
{
    int row = blockIdx.x;
    const float* xp = in + (size_t)row * Dv;
    int c4 = threadIdx.x * 4;
    float4 v = *reinterpret_cast<const float4*>(&xp[c4]);
    float s  = v.x + v.y + v.z + v.w;
    float ss = v.x * v.x + v.y * v.y + v.z * v.z + v.w * v.w;
#pragma unroll
    for (int o = 16; o > 0; o >>= 1) {
        s  += __shfl_xor_sync(0xffffffffu, s, o);
        ss += __shfl_xor_sync(0xffffffffu, ss, o);
    }
    __shared__ float sh_s[8], sh_ss[8];
    int w = threadIdx.x >> 5;
    if ((threadIdx.x & 31) == 0) { sh_s[w] = s; sh_ss[w] = ss; }
    __syncthreads();
    s = 0.f; ss = 0.f;
#pragma unroll
    for (int i = 0; i < 8; i++) { s += sh_s[i]; ss += sh_ss[i]; }
    float mean = s * (1.f / Dv);
    float var  = ss * (1.f / Dv) - mean * mean;
    float inv  = rsqrtf(var + 1e-5f);
    float4 gv = *reinterpret_cast<const float4*>(&gam[c4]);
    float4 bvv = *reinterpret_cast<const float4*>(&bet[c4]);
    float4 o;
    o.x = (v.x - mean) * inv * gv.x + bvv.x;
    o.y = (v.y - mean) * inv * gv.y + bvv.y;
    o.z = (v.z - mean) * inv * gv.z + bvv.z;
    o.w = (v.w - mean) * inv * gv.w + bvv.w;
    *reinterpret_cast<float4*>(&out[(size_t)row * Dv + c4]) = o;
    if (out_h) {
        __half2 h[2];
        h[0] = __floats2half2_rn(o.x, o.y);
        h[1] = __floats2half2_rn(o.z, o.w);
        *reinterpret_cast<uint2*>(&out_h[(size_t)row * Dv + c4]) =
            *reinterpret_cast<uint2*>(h);
    }
}

// ================= launch =================
extern "C" void kernel_launch(void* const* d_in, const int* in_sizes, int n_in,
                              void* d_out, int out_size)
{
    const float* src  = (const float*)d_in[0];
    const float* pos  = (const float*)d_in[1];
    const unsigned char* mask = (const unsigned char*)d_in[2];
    const float* refp = (const float*)d_in[3];
    const float* snip = (const float*)d_in[4];
    const float* Wv   = (const float*)d_in[5];
    const float* bv   = (const float*)d_in[6];
    const float* Woff = (const float*)d_in[7];
    const float* boff = (const float*)d_in[8];
    const float* Wa   = (const float*)d_in[9];
    const float* ba   = (const float*)d_in[10];
    const float* Wo   = (const float*)d_in[11];
    const float* bo   = (const float*)d_in[12];
    const float* W1   = (const float*)d_in[13];
    const float* b1   = (const float*)d_in[14];
    const float* W2   = (const float*)d_in[15];
    const float* b2   = (const float*)d_in[16];
    const float* g1   = (const float*)d_in[17];
    const float* be1  = (const float*)d_in[18];
    const float* g2   = (const float*)d_in[19];
    const float* be2  = (const float*)d_in[20];
    float* outp = (float*)d_out;

    float* sf = nullptr;
    __half* sh = nullptr;
    cudaGetSymbolAddress((void**)&sf, g_scratch_f);
    cudaGetSymbolAddress((void**)&sh, g_scratch_h);
    float* offa = sf + OFF_OFFA;
    float* x    = sf + OFF_X;
    float* y    = sf + OFF_Y;
    float* bofa = sf + OFF_BOFA;
    __half* srch = sh + HOFF_SRC;
    __half* qh   = sh + HOFF_Q;
    __half* valh = sh + HOFF_VAL;
    __half* aoh  = sh + HOFF_AO;
    __half* xh   = sh + HOFF_XH;
    __half* hh   = sh + HOFF_H;
    __half* wvh  = sh + HOFF_WV;
    __half* woh  = sh + HOFF_WO;
    __half* w1h  = sh + HOFF_W1;
    __half* w2h  = sh + HOFF_W2;
    __half* wofah = sh + HOFF_WOFA;

    cudaFuncSetAttribute(hmma_gemm<EPI_MASK, 1>,
        cudaFuncAttributeMaxDynamicSharedMemorySize, GSMEM_BYTES);
    cudaFuncSetAttribute(hmma_gemm<EPI_BIAS, 0>,
        cudaFuncAttributeMaxDynamicSharedMemorySize, GSMEM_BYTES);
    cudaFuncSetAttribute(hmma_gemm<EPI_RELU, 1>,
        cudaFuncAttributeMaxDynamicSharedMemorySize, GSMEM_BYTES);
    cudaFuncSetAttribute(hmma_gemm<EPI_RES, 0>,
        cudaFuncAttributeMaxDynamicSharedMemorySize, GSMEM_BYTES);

    const dim3 blk(256);

    // ---- prep: fp32 -> fp16 operand copies ----
    tohalf_k<<<(MDsz / 8) / 256, blk>>>(src, srch);
    tohalf_k<<<((size_t)Dv * Dv / 8) / 256, blk>>>(Wv, wvh);
    tohalf_k<<<((size_t)Dv * Dv / 8) / 256, blk>>>(Wo, woh);
    tohalf_k<<<((size_t)Dv * FFv / 8) / 256, blk>>>(W1, w1h);
    tohalf_k<<<((size_t)FFv * Dv / 8) / 256, blk>>>(W2, w2h);
    prep_offa_k<<<(Dv * 128) / 256, blk>>>(Woff, boff, Wa, ba, wofah, bofa);

    // q = half(src + pos)
    addhalf_k<<<(MDsz / 8) / 256, blk>>>(src, pos, qh);

    // value = src @ Wv + bv (masked) -> half
    hmma_gemm<EPI_MASK, 1><<<dim3(Dv / 128, MROWS / 128), blk, GSMEM_BYTES>>>(
        srch, wvh, bv, nullptr, mask, Dv, Dv, valh);

    // offsets + attn logits fused -> fp32 [MROWS,128]
    hmma_gemm<EPI_BIAS, 0><<<dim3(1, MROWS / 128), blk, GSMEM_BYTES>>>(
        qh, wofah, bofa, nullptr, nullptr, Dv, 128, offa);

    // softmax + grid-sample + combine -> half
    sample_k<<<(size_t)MROWS * NHv * HDv / 256, blk>>>(valh, offa, refp, snip, aoh);

    // out proj + residual(src) -> fp32 y, then LN1 (dual out)
    hmma_gemm<EPI_RES, 0><<<dim3(Dv / 128, MROWS / 128), blk, GSMEM_BYTES>>>(
        aoh, woh, bo, src, nullptr, Dv, Dv, y);
    ln_k<<<MROWS, blk>>>(y, g1, be1, x, xh);

    // FFN
    hmma_gemm<EPI_RELU, 1><<<dim3(FFv / 128, MROWS / 128), blk, GSMEM_BYTES>>>(
        xh, w1h, b1, nullptr, nullptr, Dv, FFv, hh);
    hmma_gemm<EPI_RES, 0><<<dim3(Dv / 128, MROWS / 128), blk, GSMEM_BYTES>>>(
        hh, w2h, b2, x, nullptr, FFv, Dv, y);
    ln_k<<<MROWS, blk>>>(y, g2, be2, outp, nullptr);
}

// round 12
// speedup vs baseline: 1.9393x; 1.0282x over previous
#include <cuda_runtime.h>
#include <cuda_fp16.h>
#include <cstdint>

#define LQv 2048
#define BZv 8
#define Dv 1024
#define NHv 16
#define NKv 4
#define FFv 2048
#define HDv 64
#define MROWS (LQv * BZv)   // 16384

// ================= scratch =================
#define MDsz ((size_t)MROWS * Dv)
// float blob
#define OFF_OFFA  ((size_t)0)                            // [MROWS,128]
#define OFF_X     (OFF_OFFA + (size_t)MROWS * 128)
#define OFF_Y     (OFF_X   + MDsz)
#define OFF_BOFA  (OFF_Y   + MDsz)                       // [128]
#define SCRATCH_F (OFF_BOFA + 128)
__device__ float g_scratch_f[SCRATCH_F];

// half blob (all offsets multiples of 8 -> 16B aligned)
#define HOFF_SRC   ((size_t)0)
#define HOFF_Q     (HOFF_SRC + MDsz)
#define HOFF_VAL   (HOFF_Q   + MDsz)
#define HOFF_AO    (HOFF_VAL + MDsz)
#define HOFF_XH    (HOFF_AO  + MDsz)
#define HOFF_H     (HOFF_XH  + MDsz)                     // [MROWS,FF]
#define HOFF_WV    (HOFF_H   + (size_t)MROWS * FFv)
#define HOFF_WO    (HOFF_WV  + (size_t)Dv * Dv)
#define HOFF_W1    (HOFF_WO  + (size_t)Dv * Dv)
#define HOFF_W2    (HOFF_W1  + (size_t)Dv * FFv)
#define HOFF_WOFA  (HOFF_W2  + (size_t)FFv * Dv)         // [1024,128]
#define SCRATCH_H  (HOFF_WOFA + (size_t)Dv * 128)
__device__ __half g_scratch_h[SCRATCH_H];

__device__ __forceinline__ uint32_t smem_u32(const void* p) {
    uint32_t a;
    asm("{ .reg .u64 t; cvta.to.shared.u64 t, %1; cvt.u32.u64 %0, t; }"
        : "=r"(a) : "l"(p));
    return a;
}

#define CP16(dst, src) \
    asm volatile("cp.async.cg.shared.global [%0], [%1], 16;" \
                 :: "r"(dst), "l"(src))
#define CP_COMMIT() asm volatile("cp.async.commit_group;")
#define CP_WAIT1()  asm volatile("cp.async.wait_group 1;")
#define CP_WAIT0()  asm volatile("cp.async.wait_group 0;")

#define LDSM_X4(r, addr) \
    asm volatile("ldmatrix.sync.aligned.m8n8.x4.shared.b16 {%0,%1,%2,%3}, [%4];" \
                 : "=r"((r)[0]), "=r"((r)[1]), "=r"((r)[2]), "=r"((r)[3]) \
                 : "r"(addr))
#define LDSM_X4_T(r, addr) \
    asm volatile("ldmatrix.sync.aligned.m8n8.x4.trans.shared.b16 {%0,%1,%2,%3}, [%4];" \
                 : "=r"((r)[0]), "=r"((r)[1]), "=r"((r)[2]), "=r"((r)[3]) \
                 : "r"(addr))

__device__ __forceinline__ void mma_f16(float* c, const uint32_t* a,
                                        const uint32_t* b)
{
    asm volatile(
        "mma.sync.aligned.m16n8k16.row.col.f32.f16.f16.f32 "
        "{%0,%1,%2,%3}, {%4,%5,%6,%7}, {%8,%9}, {%0,%1,%2,%3};"
        : "+f"(c[0]), "+f"(c[1]), "+f"(c[2]), "+f"(c[3])
        : "r"(a[0]), "r"(a[1]), "r"(a[2]), "r"(a[3]),
          "r"(b[0]), "r"(b[1]));
}

// ================= fp32 -> fp16 convert (8 elems/thread) =================
__global__ __launch_bounds__(256)
void tohalf_k(const float* __restrict__ a, __half* __restrict__ o)
{
    size_t i = ((size_t)blockIdx.x * 256 + threadIdx.x) * 8;
    float4 v0 = *reinterpret_cast<const float4*>(a + i);
    float4 v1 = *reinterpret_cast<const float4*>(a + i + 4);
    __half2 h[4];
    h[0] = __floats2half2_rn(v0.x, v0.y);
    h[1] = __floats2half2_rn(v0.z, v0.w);
    h[2] = __floats2half2_rn(v1.x, v1.y);
    h[3] = __floats2half2_rn(v1.z, v1.w);
    *reinterpret_cast<uint4*>(o + i) = *reinterpret_cast<uint4*>(h);
}

// fused: srch = half(src); qh = half(src + pos)  (one read of src)
__global__ __launch_bounds__(256)
void srcq_k(const float* __restrict__ src, const float* __restrict__ pos,
            __half* __restrict__ srch, __half* __restrict__ qh)
{
    size_t i = ((size_t)blockIdx.x * 256 + threadIdx.x) * 8;
    float4 a0 = *reinterpret_cast<const float4*>(src + i);
    float4 a1 = *reinterpret_cast<const float4*>(src + i + 4);
    float4 b0 = *reinterpret_cast<const float4*>(pos + i);
    float4 b1 = *reinterpret_cast<const float4*>(pos + i + 4);
    __half2 hs[4], hq[4];
    hs[0] = __floats2half2_rn(a0.x, a0.y);
    hs[1] = __floats2half2_rn(a0.z, a0.w);
    hs[2] = __floats2half2_rn(a1.x, a1.y);
    hs[3] = __floats2half2_rn(a1.z, a1.w);
    hq[0] = __floats2half2_rn(a0.x + b0.x, a0.y + b0.y);
    hq[1] = __floats2half2_rn(a0.z + b0.z, a0.w + b0.w);
    hq[2] = __floats2half2_rn(a1.x + b1.x, a1.y + b1.y);
    hq[3] = __floats2half2_rn(a1.z + b1.z, a1.w + b1.w);
    *reinterpret_cast<uint4*>(srch + i) = *reinterpret_cast<uint4*>(hs);
    *reinterpret_cast<uint4*>(qh + i)   = *reinterpret_cast<uint4*>(hq);
}

// fuse Woff|Wa -> Wofa[1024][128] half + bias concat
__global__ __launch_bounds__(256)
void prep_offa_k(const float* __restrict__ Woff, const float* __restrict__ boff,
                 const float* __restrict__ Wa,   const float* __restrict__ ba,
                 __half* __restrict__ Wofa, float* __restrict__ bout)
{
    int idx = blockIdx.x * 256 + threadIdx.x;   // 1024*128
    int k = idx >> 7, n = idx & 127;
    float v = (n < 64) ? Woff[(size_t)k * 64 + n] : Wa[(size_t)k * 64 + (n - 64)];
    Wofa[idx] = __float2half(v);
    if (idx < 128) bout[idx] = (idx < 64) ? boff[idx] : ba[idx - 64];
}

// ================= fp16 mma GEMM, BK=64 =================
// C[M,N] = A[M,K]@B[K,N] + bias (+epi). BM=128, BN=128, BK=64, 256 thr, 8 warps.
// 3-stage cp.async (107.5 KB), 2 CTA/SM. ldmatrix fragments.
enum { EPI_BIAS = 0, EPI_MASK = 1, EPI_RELU = 2, EPI_RES = 3 };

#define SA_H 72                    // A row stride in halfs (144B)
#define SB_H 136                   // B row stride in halfs (272B)
#define A_B (128 * SA_H * 2)       // 18432 B
#define B_B (64 * SB_H * 2)        // 17408 B
#define STG_B (A_B + B_B)          // 35840 B
#define GSMEM_BYTES (3 * STG_B)    // 107520 B

template <int EPI, int OUTH>
__global__ __launch_bounds__(256, 2)
void hmma_gemm(const __half* __restrict__ A, const __half* __restrict__ B,
               const float* __restrict__ bias, const float* __restrict__ res,
               const unsigned char* __restrict__ mask,
               int K, int N, void* __restrict__ Cv)
{
    extern __shared__ char sm[];
    const uint32_t sb0 = smem_u32(sm);

    const int tid = threadIdx.x;
    const int lane = tid & 31;
    const int wid = tid >> 5;
    const int warp_m = wid & 1;        // 2 warps in M (64 rows)
    const int warp_n = wid >> 1;       // 4 warps in N (32 cols)
    const int g = lane >> 2, t = lane & 3;
    const int row0 = blockIdx.y * 128;
    const int col0 = blockIdx.x * 128;

    float acc[4][4][4];
#pragma unroll
    for (int mi = 0; mi < 4; mi++)
#pragma unroll
        for (int ni = 0; ni < 4; ni++)
#pragma unroll
            for (int j = 0; j < 4; j++) acc[mi][ni][j] = 0.f;

    const int NC = K >> 6;

    auto issue = [&](int c_, int s_) {
        const __half* Ap = A + (size_t)row0 * K + (c_ << 6);
        const __half* Bp = B + (size_t)(c_ << 6) * N + col0;
        uint32_t ab = sb0 + (uint32_t)s_ * STG_B;
        uint32_t bb = ab + A_B;
#pragma unroll
        for (int it = 0; it < 4; it++) {        // A: 128 rows x 8 granules
            int id = tid + it * 256;
            int m = id >> 3, kc = id & 7;
            CP16(ab + (uint32_t)(m * (SA_H * 2) + kc * 16),
                 Ap + (size_t)m * K + kc * 8);
        }
#pragma unroll
        for (int it = 0; it < 4; it++) {        // B: 64 rows x 16 granules
            int id = tid + it * 256;
            int k = id >> 4, nc = id & 15;
            CP16(bb + (uint32_t)(k * (SB_H * 2) + nc * 16),
                 Bp + (size_t)k * N + nc * 8);
        }
        CP_COMMIT();
    };

    // ldmatrix per-thread address components
    const int rowA = (lane & 7) + 8 * ((lane >> 3) & 1);
    const int koffA = (lane >> 4) * 16;          // bytes (8 halfs)
    const int krowB = lane & 15;
    const int noffB = (lane >> 4) * 8;           // halfs

    issue(0, 0);
    issue(1, 1);

    for (int c = 0; c < NC; c++) {
        const int s = c % 3;
        if (c + 2 < NC) { CP_WAIT1(); } else { CP_WAIT0(); }
        __syncthreads();
        if (c + 2 < NC) issue(c + 2, (c + 2) % 3);

        const uint32_t ab = sb0 + (uint32_t)s * STG_B;
        const uint32_t bb = ab + A_B;
#pragma unroll
        for (int kk = 0; kk < 4; kk++) {
            uint32_t af[4][4], bf[4][2];
#pragma unroll
            for (int mi = 0; mi < 4; mi++) {
                uint32_t addr = ab +
                    (uint32_t)((warp_m * 64 + mi * 16 + rowA) * (SA_H * 2) +
                               kk * 32 + koffA);
                LDSM_X4(af[mi], addr);
            }
#pragma unroll
            for (int ni2 = 0; ni2 < 2; ni2++) {
                uint32_t r[4];
                uint32_t addr = bb +
                    (uint32_t)((kk * 16 + krowB) * (SB_H * 2) +
                               (warp_n * 32 + ni2 * 16 + noffB) * 2);
                LDSM_X4_T(r, addr);
                bf[ni2 * 2 + 0][0] = r[0]; bf[ni2 * 2 + 0][1] = r[1];
                bf[ni2 * 2 + 1][0] = r[2]; bf[ni2 * 2 + 1][1] = r[3];
            }
#pragma unroll
            for (int mi = 0; mi < 4; mi++)
#pragma unroll
                for (int ni = 0; ni < 4; ni++)
                    mma_f16(acc[mi][ni], af[mi], bf[ni]);
        }
    }

    // ---- epilogue ----
#pragma unroll
    for (int mi = 0; mi < 4; mi++) {
        int rA = row0 + warp_m * 64 + mi * 16 + g;
#pragma unroll
        for (int half_i = 0; half_i < 2; half_i++) {
            int r = rA + half_i * 8;
            unsigned char mrow = 0;
            if (EPI == EPI_MASK) {
                int b = r & (BZv - 1);
                int qq = r >> 3;
                mrow = mask[b * LQv + qq];
            }
#pragma unroll
            for (int ni = 0; ni < 4; ni++) {
                int cc = col0 + warp_n * 32 + ni * 8 + t * 2;
                float v0 = acc[mi][ni][half_i * 2 + 0] + bias[cc + 0];
                float v1 = acc[mi][ni][half_i * 2 + 1] + bias[cc + 1];
                if (EPI == EPI_MASK && mrow) { v0 = 0.f; v1 = 0.f; }
                if (EPI == EPI_RELU) { v0 = fmaxf(v0, 0.f); v1 = fmaxf(v1, 0.f); }
                if (EPI == EPI_RES) {
                    float2 rv = *reinterpret_cast<const float2*>(
                        &res[(size_t)r * N + cc]);
                    v0 += rv.x; v1 += rv.y;
                }
                if (OUTH) {
                    __half2 h = __floats2half2_rn(v0, v1);
                    *reinterpret_cast<__half2*>(
                        (__half*)Cv + (size_t)r * N + cc) = h;
                } else {
                    *reinterpret_cast<float2*>(
                        (float*)Cv + (size_t)r * N + cc) = make_float2(v0, v1);
                }
            }
        }
    }
}

// ================= softmax + grid_sample1d + head combine =================
__global__ __launch_bounds__(256)
void sample_k(const __half* __restrict__ value,  // [Lv, BZ, D] half
              const float* __restrict__ offa,    // [MROWS, 128]
              const float* __restrict__ refp,    // [BZ, LQ]
              const float* __restrict__ snip,    // [BZ]
              __half* __restrict__ out)          // [MROWS, D] half
{
    int t = blockIdx.x * 256 + threadIdx.x;
    int c = t & 63;
    int gidx = t >> 6;
    int h = gidx & (NHv - 1);
    int rb = gidx >> 4;
    int b = rb & (BZv - 1);
    int q = rb >> 3;

    const float* ol = offa + (size_t)rb * 128 + h * NKv;
    const float* al = ol + 64;

    float a0 = al[0], a1 = al[1], a2 = al[2], a3 = al[3];
    float m = fmaxf(fmaxf(a0, a1), fmaxf(a2, a3));
    float e0 = __expf(a0 - m), e1 = __expf(a1 - m);
    float e2 = __expf(a2 - m), e3 = __expf(a3 - m);
    float inv_s = 1.f / (e0 + e1 + e2 + e3);
    float ak[4] = {e0 * inv_s, e1 * inv_s, e2 * inv_s, e3 * inv_s};

    float refv = refp[b * LQv + q];
    float inv_sn = 1.f / snip[b];

    float acc = 0.f;
#pragma unroll
    for (int k = 0; k < NKv; k++) {
        float loc = refv + ol[k] * inv_sn;
        float x = loc * (float)(LQv - 1);
        float x0f = floorf(x);
        float w1 = x - x0f;
        float w0 = 1.f - w1;
        float x0c = fminf(fmaxf(x0f, -2.f), (float)(LQv + 1));
        int i0 = (int)x0c;
        int i1 = i0 + 1;
        float v0 = 0.f, v1 = 0.f;
        if (x0f >= 0.f && x0f <= (float)(LQv - 1))
            v0 = __half2float(value[((size_t)i0 * BZv + b) * Dv + h * HDv + c]);
        if (x0f >= -1.f && x0f <= (float)(LQv - 2))
            v1 = __half2float(value[((size_t)i1 * BZv + b) * Dv + h * HDv + c]);
        acc += ak[k] * (w0 * v0 + w1 * v1);
    }
    out[(size_t)rb * Dv + h * HDv + c] = __float2half(acc);
}

// ================= LayerNorm D=1024 (optional half dual output) ===========
__global__ __launch_bounds__(256)
void ln_k(const float* __restrict__ in, const float* __restrict__ gam,
          const float* __restrict__ bet, float* __restrict__ out,
          __half* __restrict__ out_h)
{
    int row = blockIdx.x;
    const float* xp = in + (size_t)row * Dv;
    int c4 = threadIdx.x * 4;
    float4 v = *reinterpret_cast<const float4*>(&xp[c4]);
    float s  = v.x + v.y + v.z + v.w;
    float ss = v.x * v.x + v.y * v.y + v.z * v.z + v.w * v.w;
#pragma unroll
    for (int o = 16; o > 0; o >>= 1) {
        s  += __shfl_xor_sync(0xffffffffu, s, o);
        ss += __shfl_xor_sync(0xffffffffu, ss, o);
    }
    __shared__ float sh_s[8], sh_ss[8];
    int w = threadIdx.x >> 5;
    if ((threadIdx.x & 31) == 0) { sh_s[w] = s; sh_ss[w] = ss; }
    __syncthreads();
    s = 0.f; ss = 0.f;
#pragma unroll
    for (int i = 0; i < 8; i++) { s += sh_s[i]; ss += sh_ss[i]; }
    float mean = s * (1.f / Dv);
    float var  = ss * (1.f / Dv) - mean * mean;
    float inv  = rsqrtf(var + 1e-5f);
    float4 gv = *reinterpret_cast<const float4*>(&gam[c4]);
    float4 bvv = *reinterpret_cast<const float4*>(&bet[c4]);
    float4 o;
    o.x = (v.x - mean) * inv * gv.x + bvv.x;
    o.y = (v.y - mean) * inv * gv.y + bvv.y;
    o.z = (v.z - mean) * inv * gv.z + bvv.z;
    o.w = (v.w - mean) * inv * gv.w + bvv.w;
    *reinterpret_cast<float4*>(&out[(size_t)row * Dv + c4]) = o;
    if (out_h) {
        __half2 h[2];
        h[0] = __floats2half2_rn(o.x, o.y);
        h[1] = __floats2half2_rn(o.z, o.w);
        *reinterpret_cast<uint2*>(&out_h[(size_t)row * Dv + c4]) =
            *reinterpret_cast<uint2*>(h);
    }
}

// ================= launch =================
extern "C" void kernel_launch(void* const* d_in, const int* in_sizes, int n_in,
                              void* d_out, int out_size)
{
    const float* src  = (const float*)d_in[0];
    const float* pos  = (const float*)d_in[1];
    const unsigned char* mask = (const unsigned char*)d_in[2];
    const float* refp = (const float*)d_in[3];
    const float* snip = (const float*)d_in[4];
    const float* Wv   = (const float*)d_in[5];
    const float* bv   = (const float*)d_in[6];
    const float* Woff = (const float*)d_in[7];
    const float* boff = (const float*)d_in[8];
    const float* Wa   = (const float*)d_in[9];
    const float* ba   = (const float*)d_in[10];
    const float* Wo   = (const float*)d_in[11];
    const float* bo   = (const float*)d_in[12];
    const float* W1   = (const float*)d_in[13];
    const float* b1   = (const float*)d_in[14];
    const float* W2   = (const float*)d_in[15];
    const float* b2   = (const float*)d_in[16];
    const float* g1   = (const float*)d_in[17];
    const float* be1  = (const float*)d_in[18];
    const float* g2   = (const float*)d_in[19];
    const float* be2  = (const float*)d_in[20];
    float* outp = (float*)d_out;

    float* sf = nullptr;
    __half* sh = nullptr;
    cudaGetSymbolAddress((void**)&sf, g_scratch_f);
    cudaGetSymbolAddress((void**)&sh, g_scratch_h);
    float* offa = sf + OFF_OFFA;
    float* x    = sf + OFF_X;
    float* y    = sf + OFF_Y;
    float* bofa = sf + OFF_BOFA;
    __half* srch = sh + HOFF_SRC;
    __half* qh   = sh + HOFF_Q;
    __half* valh = sh + HOFF_VAL;
    __half* aoh  = sh + HOFF_AO;
    __half* xh   = sh + HOFF_XH;
    __half* hh   = sh + HOFF_H;
    __half* wvh  = sh + HOFF_WV;
    __half* woh  = sh + HOFF_WO;
    __half* w1h  = sh + HOFF_W1;
    __half* w2h  = sh + HOFF_W2;
    __half* wofah = sh + HOFF_WOFA;

    cudaFuncSetAttribute(hmma_gemm<EPI_MASK, 1>,
        cudaFuncAttributeMaxDynamicSharedMemorySize, GSMEM_BYTES);
    cudaFuncSetAttribute(hmma_gemm<EPI_BIAS, 0>,
        cudaFuncAttributeMaxDynamicSharedMemorySize, GSMEM_BYTES);
    cudaFuncSetAttribute(hmma_gemm<EPI_RELU, 1>,
        cudaFuncAttributeMaxDynamicSharedMemorySize, GSMEM_BYTES);
    cudaFuncSetAttribute(hmma_gemm<EPI_RES, 0>,
        cudaFuncAttributeMaxDynamicSharedMemorySize, GSMEM_BYTES);

    const dim3 blk(256);

    // ---- prep: fp32 -> fp16 operand copies ----
    srcq_k<<<(MDsz / 8) / 256, blk>>>(src, pos, srch, qh);
    tohalf_k<<<((size_t)Dv * Dv / 8) / 256, blk>>>(Wv, wvh);
    tohalf_k<<<((size_t)Dv * Dv / 8) / 256, blk>>>(Wo, woh);
    tohalf_k<<<((size_t)Dv * FFv / 8) / 256, blk>>>(W1, w1h);
    tohalf_k<<<((size_t)FFv * Dv / 8) / 256, blk>>>(W2, w2h);
    prep_offa_k<<<(Dv * 128) / 256, blk>>>(Woff, boff, Wa, ba, wofah, bofa);

    // value = src @ Wv + bv (masked) -> half
    hmma_gemm<EPI_MASK, 1><<<dim3(Dv / 128, MROWS / 128), blk, GSMEM_BYTES>>>(
        srch, wvh, bv, nullptr, mask, Dv, Dv, valh);

    // offsets + attn logits fused -> fp32 [MROWS,128]
    hmma_gemm<EPI_BIAS, 0><<<dim3(1, MROWS / 128), blk, GSMEM_BYTES>>>(
        qh, wofah, bofa, nullptr, nullptr, Dv, 128, offa);

    // softmax + grid-sample + combine -> half
    sample_k<<<(size_t)MROWS * NHv * HDv / 256, blk>>>(valh, offa, refp, snip, aoh);

    // out proj + residual(src) -> fp32 y, then LN1 (dual out)
    hmma_gemm<EPI_RES, 0><<<dim3(Dv / 128, MROWS / 128), blk, GSMEM_BYTES>>>(
        aoh, woh, bo, src, nullptr, Dv, Dv, y);
    ln_k<<<MROWS, blk>>>(y, g1, be1, x, xh);

    // FFN
    hmma_gemm<EPI_RELU, 1><<<dim3(FFv / 128, MROWS / 128), blk, GSMEM_BYTES>>>(
        xh, w1h, b1, nullptr, nullptr, Dv, FFv, hh);
    hmma_gemm<EPI_RES, 0><<<dim3(Dv / 128, MROWS / 128), blk, GSMEM_BYTES>>>(
        hh, w2h, b2, x, nullptr, FFv, Dv, y);
    ln_k<<<MROWS, blk>>>(y, g2, be2, outp, nullptr);
}

// round 13
// speedup vs baseline: 1.9663x; 1.0139x over previous
#include <cuda_runtime.h>
#include <cuda_fp16.h>
#include <cstdint>

#define LQv 2048
#define BZv 8
#define Dv 1024
#define NHv 16
#define NKv 4
#define FFv 2048
#define HDv 64
#define MROWS (LQv * BZv)   // 16384

// ================= scratch =================
#define MDsz ((size_t)MROWS * Dv)
// float blob
#define OFF_OFFA  ((size_t)0)                            // [MROWS,128]
#define OFF_X     (OFF_OFFA + (size_t)MROWS * 128)
#define OFF_Y     (OFF_X   + MDsz)
#define OFF_BOFA  (OFF_Y   + MDsz)                       // [128]
#define SCRATCH_F (OFF_BOFA + 128)
__device__ float g_scratch_f[SCRATCH_F];

// half blob (all offsets multiples of 8 -> 16B aligned)
#define HOFF_SRC   ((size_t)0)
#define HOFF_Q     (HOFF_SRC + MDsz)
#define HOFF_VAL   (HOFF_Q   + MDsz)
#define HOFF_AO    (HOFF_VAL + MDsz)
#define HOFF_XH    (HOFF_AO  + MDsz)
#define HOFF_H     (HOFF_XH  + MDsz)                     // [MROWS,FF]
#define HOFF_WV    (HOFF_H   + (size_t)MROWS * FFv)
#define HOFF_WO    (HOFF_WV  + (size_t)Dv * Dv)
#define HOFF_W1    (HOFF_WO  + (size_t)Dv * Dv)
#define HOFF_W2    (HOFF_W1  + (size_t)Dv * FFv)
#define HOFF_WOFA  (HOFF_W2  + (size_t)FFv * Dv)         // [1024,128]
#define SCRATCH_H  (HOFF_WOFA + (size_t)Dv * 128)
__device__ __half g_scratch_h[SCRATCH_H];

__device__ __forceinline__ uint32_t smem_u32(const void* p) {
    uint32_t a;
    asm("{ .reg .u64 t; cvta.to.shared.u64 t, %1; cvt.u32.u64 %0, t; }"
        : "=r"(a) : "l"(p));
    return a;
}

#define CP16(dst, src) \
    asm volatile("cp.async.cg.shared.global [%0], [%1], 16;" \
                 :: "r"(dst), "l"(src))
#define CP_COMMIT() asm volatile("cp.async.commit_group;")
#define CP_WAIT1()  asm volatile("cp.async.wait_group 1;")
#define CP_WAIT0()  asm volatile("cp.async.wait_group 0;")

#define LDSM_X4(r, addr) \
    asm volatile("ldmatrix.sync.aligned.m8n8.x4.shared.b16 {%0,%1,%2,%3}, [%4];" \
                 : "=r"((r)[0]), "=r"((r)[1]), "=r"((r)[2]), "=r"((r)[3]) \
                 : "r"(addr))
#define LDSM_X4_T(r, addr) \
    asm volatile("ldmatrix.sync.aligned.m8n8.x4.trans.shared.b16 {%0,%1,%2,%3}, [%4];" \
                 : "=r"((r)[0]), "=r"((r)[1]), "=r"((r)[2]), "=r"((r)[3]) \
                 : "r"(addr))

__device__ __forceinline__ void mma_f16(float* c, const uint32_t* a,
                                        const uint32_t* b)
{
    asm volatile(
        "mma.sync.aligned.m16n8k16.row.col.f32.f16.f16.f32 "
        "{%0,%1,%2,%3}, {%4,%5,%6,%7}, {%8,%9}, {%0,%1,%2,%3};"
        : "+f"(c[0]), "+f"(c[1]), "+f"(c[2]), "+f"(c[3])
        : "r"(a[0]), "r"(a[1]), "r"(a[2]), "r"(a[3]),
          "r"(b[0]), "r"(b[1]));
}

// ================= fp32 -> fp16 convert (8 elems/thread) =================
__global__ __launch_bounds__(256)
void tohalf_k(const float* __restrict__ a, __half* __restrict__ o)
{
    size_t i = ((size_t)blockIdx.x * 256 + threadIdx.x) * 8;
    float4 v0 = *reinterpret_cast<const float4*>(a + i);
    float4 v1 = *reinterpret_cast<const float4*>(a + i + 4);
    __half2 h[4];
    h[0] = __floats2half2_rn(v0.x, v0.y);
    h[1] = __floats2half2_rn(v0.z, v0.w);
    h[2] = __floats2half2_rn(v1.x, v1.y);
    h[3] = __floats2half2_rn(v1.z, v1.w);
    *reinterpret_cast<uint4*>(o + i) = *reinterpret_cast<uint4*>(h);
}

// fused: srch = half(src); qh = half(src + pos)  (one read of src)
__global__ __launch_bounds__(256)
void srcq_k(const float* __restrict__ src, const float* __restrict__ pos,
            __half* __restrict__ srch, __half* __restrict__ qh)
{
    size_t i = ((size_t)blockIdx.x * 256 + threadIdx.x) * 8;
    float4 a0 = *reinterpret_cast<const float4*>(src + i);
    float4 a1 = *reinterpret_cast<const float4*>(src + i + 4);
    float4 b0 = *reinterpret_cast<const float4*>(pos + i);
    float4 b1 = *reinterpret_cast<const float4*>(pos + i + 4);
    __half2 hs[4], hq[4];
    hs[0] = __floats2half2_rn(a0.x, a0.y);
    hs[1] = __floats2half2_rn(a0.z, a0.w);
    hs[2] = __floats2half2_rn(a1.x, a1.y);
    hs[3] = __floats2half2_rn(a1.z, a1.w);
    hq[0] = __floats2half2_rn(a0.x + b0.x, a0.y + b0.y);
    hq[1] = __floats2half2_rn(a0.z + b0.z, a0.w + b0.w);
    hq[2] = __floats2half2_rn(a1.x + b1.x, a1.y + b1.y);
    hq[3] = __floats2half2_rn(a1.z + b1.z, a1.w + b1.w);
    *reinterpret_cast<uint4*>(srch + i) = *reinterpret_cast<uint4*>(hs);
    *reinterpret_cast<uint4*>(qh + i)   = *reinterpret_cast<uint4*>(hq);
}

// fuse Woff|Wa -> Wofa[1024][128] half + bias concat
__global__ __launch_bounds__(256)
void prep_offa_k(const float* __restrict__ Woff, const float* __restrict__ boff,
                 const float* __restrict__ Wa,   const float* __restrict__ ba,
                 __half* __restrict__ Wofa, float* __restrict__ bout)
{
    int idx = blockIdx.x * 256 + threadIdx.x;   // 1024*128
    int k = idx >> 7, n = idx & 127;
    float v = (n < 64) ? Woff[(size_t)k * 64 + n] : Wa[(size_t)k * 64 + (n - 64)];
    Wofa[idx] = __float2half(v);
    if (idx < 128) bout[idx] = (idx < 64) ? boff[idx] : ba[idx - 64];
}

// ================= fp16 mma GEMM, BK=64 =================
enum { EPI_BIAS = 0, EPI_MASK = 1, EPI_RELU = 2, EPI_RES = 3 };

#define SA_H 72                    // A row stride in halfs (144B)
#define SB_H 136                   // B row stride in halfs (272B)
#define A_B (128 * SA_H * 2)       // 18432 B
#define B_B (64 * SB_H * 2)        // 17408 B
#define STG_B (A_B + B_B)          // 35840 B
#define GSMEM_BYTES (3 * STG_B)    // 107520 B

template <int EPI, int OUTH>
__global__ __launch_bounds__(256, 2)
void hmma_gemm(const __half* __restrict__ A, const __half* __restrict__ B,
               const float* __restrict__ bias, const float* __restrict__ res,
               const unsigned char* __restrict__ mask,
               int K, int N, void* __restrict__ Cv)
{
    extern __shared__ char sm[];
    const uint32_t sb0 = smem_u32(sm);

    const int tid = threadIdx.x;
    const int lane = tid & 31;
    const int wid = tid >> 5;
    const int warp_m = wid & 1;
    const int warp_n = wid >> 1;
    const int g = lane >> 2, t = lane & 3;
    const int row0 = blockIdx.y * 128;
    const int col0 = blockIdx.x * 128;

    float acc[4][4][4];
#pragma unroll
    for (int mi = 0; mi < 4; mi++)
#pragma unroll
        for (int ni = 0; ni < 4; ni++)
#pragma unroll
            for (int j = 0; j < 4; j++) acc[mi][ni][j] = 0.f;

    const int NC = K >> 6;

    auto issue = [&](int c_, int s_) {
        const __half* Ap = A + (size_t)row0 * K + (c_ << 6);
        const __half* Bp = B + (size_t)(c_ << 6) * N + col0;
        uint32_t ab = sb0 + (uint32_t)s_ * STG_B;
        uint32_t bb = ab + A_B;
#pragma unroll
        for (int it = 0; it < 4; it++) {
            int id = tid + it * 256;
            int m = id >> 3, kc = id & 7;
            CP16(ab + (uint32_t)(m * (SA_H * 2) + kc * 16),
                 Ap + (size_t)m * K + kc * 8);
        }
#pragma unroll
        for (int it = 0; it < 4; it++) {
            int id = tid + it * 256;
            int k = id >> 4, nc = id & 15;
            CP16(bb + (uint32_t)(k * (SB_H * 2) + nc * 16),
                 Bp + (size_t)k * N + nc * 8);
        }
        CP_COMMIT();
    };

    const int rowA = (lane & 7) + 8 * ((lane >> 3) & 1);
    const int koffA = (lane >> 4) * 16;
    const int krowB = lane & 15;
    const int noffB = (lane >> 4) * 8;

    issue(0, 0);
    issue(1, 1);

    for (int c = 0; c < NC; c++) {
        const int s = c % 3;
        if (c + 2 < NC) { CP_WAIT1(); } else { CP_WAIT0(); }
        __syncthreads();
        if (c + 2 < NC) issue(c + 2, (c + 2) % 3);

        const uint32_t ab = sb0 + (uint32_t)s * STG_B;
        const uint32_t bb = ab + A_B;
#pragma unroll
        for (int kk = 0; kk < 4; kk++) {
            uint32_t af[4][4], bf[4][2];
#pragma unroll
            for (int mi = 0; mi < 4; mi++) {
                uint32_t addr = ab +
                    (uint32_t)((warp_m * 64 + mi * 16 + rowA) * (SA_H * 2) +
                               kk * 32 + koffA);
                LDSM_X4(af[mi], addr);
            }
#pragma unroll
            for (int ni2 = 0; ni2 < 2; ni2++) {
                uint32_t r[4];
                uint32_t addr = bb +
                    (uint32_t)((kk * 16 + krowB) * (SB_H * 2) +
                               (warp_n * 32 + ni2 * 16 + noffB) * 2);
                LDSM_X4_T(r, addr);
                bf[ni2 * 2 + 0][0] = r[0]; bf[ni2 * 2 + 0][1] = r[1];
                bf[ni2 * 2 + 1][0] = r[2]; bf[ni2 * 2 + 1][1] = r[3];
            }
#pragma unroll
            for (int mi = 0; mi < 4; mi++)
#pragma unroll
                for (int ni = 0; ni < 4; ni++)
                    mma_f16(acc[mi][ni], af[mi], bf[ni]);
        }
    }

    // ---- epilogue ----
#pragma unroll
    for (int mi = 0; mi < 4; mi++) {
        int rA = row0 + warp_m * 64 + mi * 16 + g;
#pragma unroll
        for (int half_i = 0; half_i < 2; half_i++) {
            int r = rA + half_i * 8;
            unsigned char mrow = 0;
            if (EPI == EPI_MASK) {
                int b = r & (BZv - 1);
                int qq = r >> 3;
                mrow = mask[b * LQv + qq];
            }
#pragma unroll
            for (int ni = 0; ni < 4; ni++) {
                int cc = col0 + warp_n * 32 + ni * 8 + t * 2;
                float v0 = acc[mi][ni][half_i * 2 + 0] + bias[cc + 0];
                float v1 = acc[mi][ni][half_i * 2 + 1] + bias[cc + 1];
                if (EPI == EPI_MASK && mrow) { v0 = 0.f; v1 = 0.f; }
                if (EPI == EPI_RELU) { v0 = fmaxf(v0, 0.f); v1 = fmaxf(v1, 0.f); }
                if (EPI == EPI_RES) {
                    float2 rv = *reinterpret_cast<const float2*>(
                        &res[(size_t)r * N + cc]);
                    v0 += rv.x; v1 += rv.y;
                }
                if (OUTH) {
                    __half2 h = __floats2half2_rn(v0, v1);
                    *reinterpret_cast<__half2*>(
                        (__half*)Cv + (size_t)r * N + cc) = h;
                } else {
                    *reinterpret_cast<float2*>(
                        (float*)Cv + (size_t)r * N + cc) = make_float2(v0, v1);
                }
            }
        }
    }
}

// ================= softmax + grid_sample1d + head combine =================
__global__ __launch_bounds__(256)
void sample_k(const __half* __restrict__ value,
              const float* __restrict__ offa,
              const float* __restrict__ refp,
              const float* __restrict__ snip,
              __half* __restrict__ out)
{
    int t = blockIdx.x * 256 + threadIdx.x;
    int c = t & 63;
    int gidx = t >> 6;
    int h = gidx & (NHv - 1);
    int rb = gidx >> 4;
    int b = rb & (BZv - 1);
    int q = rb >> 3;

    const float* ol = offa + (size_t)rb * 128 + h * NKv;
    const float* al = ol + 64;

    float a0 = al[0], a1 = al[1], a2 = al[2], a3 = al[3];
    float m = fmaxf(fmaxf(a0, a1), fmaxf(a2, a3));
    float e0 = __expf(a0 - m), e1 = __expf(a1 - m);
    float e2 = __expf(a2 - m), e3 = __expf(a3 - m);
    float inv_s = 1.f / (e0 + e1 + e2 + e3);
    float ak[4] = {e0 * inv_s, e1 * inv_s, e2 * inv_s, e3 * inv_s};

    float refv = refp[b * LQv + q];
    float inv_sn = 1.f / snip[b];

    float acc = 0.f;
#pragma unroll
    for (int k = 0; k < NKv; k++) {
        float loc = refv + ol[k] * inv_sn;
        float x = loc * (float)(LQv - 1);
        float x0f = floorf(x);
        float w1 = x - x0f;
        float w0 = 1.f - w1;
        float x0c = fminf(fmaxf(x0f, -2.f), (float)(LQv + 1));
        int i0 = (int)x0c;
        int i1 = i0 + 1;
        float v0 = 0.f, v1 = 0.f;
        if (x0f >= 0.f && x0f <= (float)(LQv - 1))
            v0 = __half2float(value[((size_t)i0 * BZv + b) * Dv + h * HDv + c]);
        if (x0f >= -1.f && x0f <= (float)(LQv - 2))
            v1 = __half2float(value[((size_t)i1 * BZv + b) * Dv + h * HDv + c]);
        acc += ak[k] * (w0 * v0 + w1 * v1);
    }
    out[(size_t)rb * Dv + h * HDv + c] = __float2half(acc);
}

// ================= LayerNorm D=1024 (optional half dual output) ===========
__global__ __launch_bounds__(256)
void ln_k(const float* __restrict__ in, const float* __restrict__ gam,
          const float* __restrict__ bet, float* __restrict__ out,
          __half* __restrict__ out_h)
{
    int row = blockIdx.x;
    const float* xp = in + (size_t)row * Dv;
    int c4 = threadIdx.x * 4;
    float4 v = *reinterpret_cast<const float4*>(&xp[c4]);
    float s  = v.x + v.y + v.z + v.w;
    float ss = v.x * v.x + v.y * v.y + v.z * v.z + v.w * v.w;
#pragma unroll
    for (int o = 16; o > 0; o >>= 1) {
        s  += __shfl_xor_sync(0xffffffffu, s, o);
        ss += __shfl_xor_sync(0xffffffffu, ss, o);
    }
    __shared__ float sh_s[8], sh_ss[8];
    int w = threadIdx.x >> 5;
    if ((threadIdx.x & 31) == 0) { sh_s[w] = s; sh_ss[w] = ss; }
    __syncthreads();
    s = 0.f; ss = 0.f;
#pragma unroll
    for (int i = 0; i < 8; i++) { s += sh_s[i]; ss += sh_ss[i]; }
    float mean = s * (1.f / Dv);
    float var  = ss * (1.f / Dv) - mean * mean;
    float inv  = rsqrtf(var + 1e-5f);
    float4 gv = *reinterpret_cast<const float4*>(&gam[c4]);
    float4 bvv = *reinterpret_cast<const float4*>(&bet[c4]);
    float4 o;
    o.x = (v.x - mean) * inv * gv.x + bvv.x;
    o.y = (v.y - mean) * inv * gv.y + bvv.y;
    o.z = (v.z - mean) * inv * gv.z + bvv.z;
    o.w = (v.w - mean) * inv * gv.w + bvv.w;
    *reinterpret_cast<float4*>(&out[(size_t)row * Dv + c4]) = o;
    if (out_h) {
        __half2 h[2];
        h[0] = __floats2half2_rn(o.x, o.y);
        h[1] = __floats2half2_rn(o.z, o.w);
        *reinterpret_cast<uint2*>(&out_h[(size_t)row * Dv + c4]) =
            *reinterpret_cast<uint2*>(h);
    }
}

// ================= launch =================
extern "C" void kernel_launch(void* const* d_in, const int* in_sizes, int n_in,
                              void* d_out, int out_size)
{
    const float* src  = (const float*)d_in[0];
    const float* pos  = (const float*)d_in[1];
    const unsigned char* mask = (const unsigned char*)d_in[2];
    const float* refp = (const float*)d_in[3];
    const float* snip = (const float*)d_in[4];
    const float* Wv   = (const float*)d_in[5];
    const float* bv   = (const float*)d_in[6];
    const float* Woff = (const float*)d_in[7];
    const float* boff = (const float*)d_in[8];
    const float* Wa   = (const float*)d_in[9];
    const float* ba   = (const float*)d_in[10];
    const float* Wo   = (const float*)d_in[11];
    const float* bo   = (const float*)d_in[12];
    const float* W1   = (const float*)d_in[13];
    const float* b1   = (const float*)d_in[14];
    const float* W2   = (const float*)d_in[15];
    const float* b2   = (const float*)d_in[16];
    const float* g1   = (const float*)d_in[17];
    const float* be1  = (const float*)d_in[18];
    const float* g2   = (const float*)d_in[19];
    const float* be2  = (const float*)d_in[20];
    float* outp = (float*)d_out;

    float* sf = nullptr;
    __half* sh = nullptr;
    cudaGetSymbolAddress((void**)&sf, g_scratch_f);
    cudaGetSymbolAddress((void**)&sh, g_scratch_h);
    float* offa = sf + OFF_OFFA;
    float* x    = sf + OFF_X;
    float* y    = sf + OFF_Y;
    float* bofa = sf + OFF_BOFA;
    __half* srch = sh + HOFF_SRC;
    __half* qh   = sh + HOFF_Q;
    __half* valh = sh + HOFF_VAL;
    __half* aoh  = sh + HOFF_AO;
    __half* xh   = sh + HOFF_XH;
    __half* hh   = sh + HOFF_H;
    __half* wvh  = sh + HOFF_WV;
    __half* woh  = sh + HOFF_WO;
    __half* w1h  = sh + HOFF_W1;
    __half* w2h  = sh + HOFF_W2;
    __half* wofah = sh + HOFF_WOFA;

    static cudaStream_t s_aux = nullptr;
    static cudaEvent_t ev_root, ev_q, ev_wv, ev_offa, ev_w;
    if (!s_aux) {
        cudaStreamCreateWithFlags(&s_aux, cudaStreamNonBlocking);
        cudaEventCreateWithFlags(&ev_root, cudaEventDisableTiming);
        cudaEventCreateWithFlags(&ev_q,    cudaEventDisableTiming);
        cudaEventCreateWithFlags(&ev_wv,   cudaEventDisableTiming);
        cudaEventCreateWithFlags(&ev_offa, cudaEventDisableTiming);
        cudaEventCreateWithFlags(&ev_w,    cudaEventDisableTiming);
        cudaFuncSetAttribute(hmma_gemm<EPI_MASK, 1>,
            cudaFuncAttributeMaxDynamicSharedMemorySize, GSMEM_BYTES);
        cudaFuncSetAttribute(hmma_gemm<EPI_BIAS, 0>,
            cudaFuncAttributeMaxDynamicSharedMemorySize, GSMEM_BYTES);
        cudaFuncSetAttribute(hmma_gemm<EPI_RELU, 1>,
            cudaFuncAttributeMaxDynamicSharedMemorySize, GSMEM_BYTES);
        cudaFuncSetAttribute(hmma_gemm<EPI_RES, 0>,
            cudaFuncAttributeMaxDynamicSharedMemorySize, GSMEM_BYTES);
    }

    const dim3 blk(256);

    // fork: aux starts after the graph root
    cudaEventRecord(ev_root, 0);
    cudaStreamWaitEvent(s_aux, ev_root, 0);

    // main: srch + qh (one pass over src/pos)
    srcq_k<<<(MDsz / 8) / 256, blk>>>(src, pos, srch, qh);
    cudaEventRecord(ev_q, 0);

    // aux: Wv conversion + offa weight prep (concurrent with srcq)
    tohalf_k<<<((size_t)Dv * Dv / 8) / 256, blk, 0, s_aux>>>(Wv, wvh);
    cudaEventRecord(ev_wv, s_aux);
    prep_offa_k<<<(Dv * 128) / 256, blk, 0, s_aux>>>(Woff, boff, Wa, ba,
                                                     wofah, bofa);

    // aux: offa GEMM (needs qh) — concurrent with the value GEMM on main
    cudaStreamWaitEvent(s_aux, ev_q, 0);
    hmma_gemm<EPI_BIAS, 0><<<dim3(1, MROWS / 128), blk, GSMEM_BYTES, s_aux>>>(
        qh, wofah, bofa, nullptr, nullptr, Dv, 128, offa);
    cudaEventRecord(ev_offa, s_aux);

    // aux: remaining weight conversions (hidden under value GEMM)
    tohalf_k<<<((size_t)Dv * Dv / 8) / 256, blk, 0, s_aux>>>(Wo, woh);
    tohalf_k<<<((size_t)Dv * FFv / 8) / 256, blk, 0, s_aux>>>(W1, w1h);
    tohalf_k<<<((size_t)FFv * Dv / 8) / 256, blk, 0, s_aux>>>(W2, w2h);
    cudaEventRecord(ev_w, s_aux);

    // main: value GEMM (needs srch + wvh)
    cudaStreamWaitEvent(0, ev_wv, 0);
    hmma_gemm<EPI_MASK, 1><<<dim3(Dv / 128, MROWS / 128), blk, GSMEM_BYTES>>>(
        srch, wvh, bv, nullptr, mask, Dv, Dv, valh);

    // main: sample (needs valh + offa)
    cudaStreamWaitEvent(0, ev_offa, 0);
    sample_k<<<(size_t)MROWS * NHv * HDv / 256, blk>>>(valh, offa, refp,
                                                       snip, aoh);

    // main: out proj + residual(src) -> y, LN1 (needs woh)
    cudaStreamWaitEvent(0, ev_w, 0);
    hmma_gemm<EPI_RES, 0><<<dim3(Dv / 128, MROWS / 128), blk, GSMEM_BYTES>>>(
        aoh, woh, bo, src, nullptr, Dv, Dv, y);
    ln_k<<<MROWS, blk>>>(y, g1, be1, x, xh);

    // FFN
    hmma_gemm<EPI_RELU, 1><<<dim3(FFv / 128, MROWS / 128), blk, GSMEM_BYTES>>>(
        xh, w1h, b1, nullptr, nullptr, Dv, FFv, hh);
    hmma_gemm<EPI_RES, 0><<<dim3(Dv / 128, MROWS / 128), blk, GSMEM_BYTES>>>(
        hh, w2h, b2, x, nullptr, FFv, Dv, y);
    ln_k<<<MROWS, blk>>>(y, g2, be2, outp, nullptr);
}